// round 4
// baseline (speedup 1.0000x reference)
#include <cuda_runtime.h>
#include <math.h>

#define BB   4
#define CC   512
#define NBK  8
#define BSZ  64
#define HH   128
#define WW   128
#define WFM  33
#define KHM  64
#define NPTS (BB*KHM*WFM)     // 8448

#define BIN0_IM_W 0.0f        // pocketfft: imag of kw=0 bin discarded in C2R

// ------------------------- static device scratch ---------------------------
__device__ float2 g_F[BB*CC*WFM*HH];     // (b,c,wf,h) fwd W-stage
__device__ float  g_Zr[NBK*NPTS*BSZ];
__device__ float  g_Zi[NBK*NPTS*BSZ];
__device__ float  g_Dr[NBK*NPTS*BSZ];
__device__ float  g_Di[NBK*NPTS*BSZ];
__device__ float2 g_G[BB*CC*WFM*HH];     // (b,c,wf,h) inv H-stage
__device__ float  g_S[BB*CC*HH*WW];      // x + irfft2(D)

// ---------------------------------------------------------------------------
// K1: F[bc,wf,h] = sum_w x[bc,h,w] e^{-2pi i w wf/128}, wf<33
// ---------------------------------------------------------------------------
__global__ __launch_bounds__(288) void k1_fwd_w(const float* __restrict__ x) {
  extern __shared__ float sm1[];
  float* xs  = sm1;            // [128 w][132]
  float* twc = sm1 + 16896;
  float* tws = sm1 + 17024;
  int bc = blockIdx.x, tid = threadIdx.x;
  const float* xp = x + (size_t)bc * 16384;
  for (int idx = tid; idx < 16384; idx += 288) {
    int h = idx >> 7, w = idx & 127;
    xs[w*132 + h] = xp[idx];
  }
  if (tid < 128) { float s,c; sincospif((float)tid*(1.0f/64.0f),&s,&c); twc[tid]=c; tws[tid]=s; }
  __syncthreads();

  int wf0 = (tid >> 5) * 4;       // 0..32 (last tile partially valid)
  int h0  = (tid & 31) * 4;
  float fr[4][4], fi[4][4];
  #pragma unroll
  for (int j=0;j<4;++j) {
    #pragma unroll
    for (int u=0;u<4;++u){ fr[j][u]=0.f; fi[j][u]=0.f; }
  }

  for (int w = 0; w < 128; ++w) {
    float4 a4 = *(float4*)&xs[w*132 + h0];
    float a[4] = {a4.x, a4.y, a4.z, a4.w};
    #pragma unroll
    for (int j=0;j<4;++j) {
      int m = (w*(wf0+j)) & 127;
      float c = twc[m], s = tws[m];
      #pragma unroll
      for (int u=0;u<4;++u){ fr[j][u]+=a[u]*c; fi[j][u]-=a[u]*s; }
    }
  }
  float2* Fp = g_F + (size_t)bc*(WFM*HH);
  #pragma unroll
  for (int j=0;j<4;++j) {
    int wf = wf0+j;
    if (wf < WFM) {
      #pragma unroll
      for (int u=0;u<4;++u) Fp[wf*128 + h0+u] = make_float2(fr[j][u], fi[j][u]);
    }
  }
}

// ---------------------------------------------------------------------------
// K2: Z[k] = (1/128) sum_h F[h] e^{-2pi i h k/128}, k<64. block=(b,n,wf)
// ---------------------------------------------------------------------------
__global__ __launch_bounds__(256) void k2_fwd_h() {
  extern __shared__ float sm2[];
  float* fr  = sm2;              // [64 i][133]
  float* fi  = sm2 + 8512;
  float* twc = sm2 + 17024;
  float* tws = sm2 + 17152;
  int bx = blockIdx.x;
  int wfi = bx % 33; int t = bx / 33; int n = t & 7; int b = t >> 3;
  int tid = threadIdx.x;
  const float2* Fb = g_F + ((size_t)(b*CC + n*BSZ)*WFM + wfi)*HH;
  for (int idx = tid; idx < 8192; idx += 256) {
    int i = idx >> 7, h = idx & 127;
    float2 v = Fb[(size_t)i*(WFM*HH) + h];
    fr[i*133 + h] = v.x; fi[i*133 + h] = v.y;
  }
  if (tid < 128) { float s,c; sincospif((float)tid*(1.0f/64.0f),&s,&c); twc[tid]=c; tws[tid]=s; }
  __syncthreads();

  int i0 = (tid & 15) * 4, k0 = (tid >> 4) * 4;
  float zr[4][4], zi[4][4];
  #pragma unroll
  for (int kk=0;kk<4;++kk) {
    #pragma unroll
    for (int u=0;u<4;++u){ zr[kk][u]=0.f; zi[kk][u]=0.f; }
  }

  for (int h = 0; h < 128; ++h) {
    float ar[4], ai[4];
    #pragma unroll
    for (int u=0;u<4;++u){ ar[u]=fr[(i0+u)*133+h]; ai[u]=fi[(i0+u)*133+h]; }
    #pragma unroll
    for (int kk=0;kk<4;++kk) {
      int m = (h*(k0+kk)) & 127;
      float c = twc[m], s = tws[m];
      #pragma unroll
      for (int u=0;u<4;++u) {
        zr[kk][u] += ar[u]*c + ai[u]*s;
        zi[kk][u] += ai[u]*c - ar[u]*s;
      }
    }
  }
  const float sc = 1.0f/128.0f;
  #pragma unroll
  for (int kk=0;kk<4;++kk) {
    int p = (b*KHM + k0+kk)*WFM + wfi;
    size_t base = ((size_t)n*NPTS + p)*BSZ + i0;
    *(float4*)(g_Zr+base) = make_float4(zr[kk][0]*sc, zr[kk][1]*sc, zr[kk][2]*sc, zr[kk][3]*sc);
    *(float4*)(g_Zi+base) = make_float4(zi[kk][0]*sc, zi[kk][1]*sc, zi[kk][2]*sc, zi[kk][3]*sc);
  }
}

// ---------------------------------------------------------------------------
// K3: D = softshrink(W2 @ gelu(W1 @ z + b1) + b2) - z, per block n.
// ---------------------------------------------------------------------------
__device__ __forceinline__ float gelu_f(float v) {
  return 0.5f*v*(1.0f + erff(v*0.70710678118654752f));
}
__device__ __forceinline__ float sshrink_f(float v) {
  float a = fabsf(v) - 0.01f;
  return a > 0.0f ? copysignf(a, v) : 0.0f;
}

__global__ __launch_bounds__(256) void k3_mlp(
    const float* __restrict__ w1r, const float* __restrict__ w1i,
    const float* __restrict__ b1r, const float* __restrict__ b1i,
    const float* __restrict__ w2r, const float* __restrict__ w2i,
    const float* __restrict__ b2r, const float* __restrict__ b2i) {
  extern __shared__ float sm3[];
  float* wsr = sm3;            float* wsi = sm3 + 4096;
  float* zsr = sm3 + 8192;     float* zsi = sm3 + 12352;   // [64 p][65]
  float* hsr = sm3 + 16512;    float* hsi = sm3 + 20672;   // [64 p][65]
  float* bs  = sm3 + 24832;
  int bx = blockIdx.x;
  int n = bx / 132, pt = bx % 132;
  int tid = threadIdx.x;
  size_t zbase = ((size_t)n*NPTS + (size_t)pt*64)*64;

  for (int idx = tid; idx < 4096; idx += 256) {
    int p = idx >> 6, i = idx & 63;
    wsr[idx] = w1r[n*4096 + idx]; wsi[idx] = w1i[n*4096 + idx];
    zsr[p*65+i] = g_Zr[zbase + idx]; zsi[p*65+i] = g_Zi[zbase + idx];
  }
  if (tid < 64) {
    bs[tid]     = b1r[n*64+tid]; bs[64+tid]  = b1i[n*64+tid];
    bs[128+tid] = b2r[n*64+tid]; bs[192+tid] = b2i[n*64+tid];
  }
  __syncthreads();

  int j0 = (tid & 15) * 4, p0 = (tid >> 4) * 4;
  float hr[4][4], hi2[4][4];
  #pragma unroll
  for (int u=0;u<4;++u) {
    #pragma unroll
    for (int v=0;v<4;++v){ hr[u][v]=bs[j0+v]; hi2[u][v]=bs[64+j0+v]; }
  }

  for (int i = 0; i < 64; ++i) {
    float zr[4], zi2[4], wr[4], wi2[4];
    #pragma unroll
    for (int u=0;u<4;++u){ zr[u]=zsr[(p0+u)*65+i]; zi2[u]=zsi[(p0+u)*65+i]; }
    float4 w4r = *(float4*)&wsr[i*64+j0];
    float4 w4i = *(float4*)&wsi[i*64+j0];
    wr[0]=w4r.x; wr[1]=w4r.y; wr[2]=w4r.z; wr[3]=w4r.w;
    wi2[0]=w4i.x; wi2[1]=w4i.y; wi2[2]=w4i.z; wi2[3]=w4i.w;
    #pragma unroll
    for (int u=0;u<4;++u) {
      #pragma unroll
      for (int v=0;v<4;++v){
        hr[u][v]  += zr[u]*wr[v]  - zi2[u]*wi2[v];
        hi2[u][v] += zr[u]*wi2[v] + zi2[u]*wr[v];
      }
    }
  }
  #pragma unroll
  for (int u=0;u<4;++u) {
    #pragma unroll
    for (int v=0;v<4;++v){
      hsr[(p0+u)*65 + j0+v] = gelu_f(hr[u][v]);
      hsi[(p0+u)*65 + j0+v] = gelu_f(hi2[u][v]);
    }
  }
  __syncthreads();
  for (int idx = tid; idx < 4096; idx += 256) {
    wsr[idx] = w2r[n*4096 + idx]; wsi[idx] = w2i[n*4096 + idx];
  }
  __syncthreads();

  float yr[4][4], yi[4][4];
  #pragma unroll
  for (int u=0;u<4;++u) {
    #pragma unroll
    for (int v=0;v<4;++v){ yr[u][v]=bs[128+j0+v]; yi[u][v]=bs[192+j0+v]; }
  }

  for (int i = 0; i < 64; ++i) {
    float ar[4], ai[4], wr[4], wi2[4];
    #pragma unroll
    for (int u=0;u<4;++u){ ar[u]=hsr[(p0+u)*65+i]; ai[u]=hsi[(p0+u)*65+i]; }
    float4 w4r = *(float4*)&wsr[i*64+j0];
    float4 w4i = *(float4*)&wsi[i*64+j0];
    wr[0]=w4r.x; wr[1]=w4r.y; wr[2]=w4r.z; wr[3]=w4r.w;
    wi2[0]=w4i.x; wi2[1]=w4i.y; wi2[2]=w4i.z; wi2[3]=w4i.w;
    #pragma unroll
    for (int u=0;u<4;++u) {
      #pragma unroll
      for (int v=0;v<4;++v){
        yr[u][v] += ar[u]*wr[v]  - ai[u]*wi2[v];
        yi[u][v] += ar[u]*wi2[v] + ai[u]*wr[v];
      }
    }
  }
  #pragma unroll
  for (int u=0;u<4;++u) {
    float4 dr, di;
    dr.x = sshrink_f(yr[u][0]) - zsr[(p0+u)*65 + j0+0];
    dr.y = sshrink_f(yr[u][1]) - zsr[(p0+u)*65 + j0+1];
    dr.z = sshrink_f(yr[u][2]) - zsr[(p0+u)*65 + j0+2];
    dr.w = sshrink_f(yr[u][3]) - zsr[(p0+u)*65 + j0+3];
    di.x = sshrink_f(yi[u][0]) - zsi[(p0+u)*65 + j0+0];
    di.y = sshrink_f(yi[u][1]) - zsi[(p0+u)*65 + j0+1];
    di.z = sshrink_f(yi[u][2]) - zsi[(p0+u)*65 + j0+2];
    di.w = sshrink_f(yi[u][3]) - zsi[(p0+u)*65 + j0+3];
    size_t ob = zbase + (size_t)(p0+u)*64 + j0;
    *(float4*)(g_Dr+ob) = dr;
    *(float4*)(g_Di+ob) = di;
  }
}

// ---------------------------------------------------------------------------
// K4: G[h] = sum_{k<64} D[k] e^{+2pi i h k/128}. block=(b,n,wf); 256 thr.
// ---------------------------------------------------------------------------
__global__ __launch_bounds__(256) void k4_inv_h() {
  __shared__ float dsr[4096], dsi[4096], twc[128], tws[128];
  int bx = blockIdx.x;
  int wfi = bx % 33; int t = bx / 33; int n = t & 7; int b = t >> 3;
  int tid = threadIdx.x;
  size_t base = ((size_t)n*NPTS + (size_t)(b*KHM)*WFM + wfi)*64;
  for (int idx = tid; idx < 4096; idx += 256) {
    int k = idx >> 6, i = idx & 63;
    dsr[idx] = g_Dr[base + (size_t)k*(WFM*64) + i];
    dsi[idx] = g_Di[base + (size_t)k*(WFM*64) + i];
  }
  if (tid < 128) { float s,c; sincospif((float)tid*(1.0f/64.0f),&s,&c); twc[tid]=c; tws[tid]=s; }
  __syncthreads();

  int h0 = (tid & 15) * 8, i0 = (tid >> 4) * 4;
  float gre[4][8], gim[4][8];
  #pragma unroll
  for (int u=0;u<4;++u) {
    #pragma unroll
    for (int q=0;q<8;++q){ gre[u][q]=0.f; gim[u][q]=0.f; }
  }

  for (int k = 0; k < 64; ++k) {
    float4 r4 = *(float4*)&dsr[k*64 + i0];
    float4 i4 = *(float4*)&dsi[k*64 + i0];
    float dr[4]={r4.x,r4.y,r4.z,r4.w}, di[4]={i4.x,i4.y,i4.z,i4.w};
    #pragma unroll
    for (int q=0;q<8;++q) {
      int m = ((h0+q)*k) & 127;
      float c = twc[m], s = tws[m];
      #pragma unroll
      for (int u=0;u<4;++u) {
        gre[u][q] += dr[u]*c - di[u]*s;
        gim[u][q] += dr[u]*s + di[u]*c;
      }
    }
  }
  #pragma unroll
  for (int u=0;u<4;++u) {
    float2* Gp = g_G + ((size_t)(b*CC + n*BSZ + i0+u)*WFM + wfi)*HH + h0;
    #pragma unroll
    for (int q=0;q<8;++q) Gp[q] = make_float2(gre[u][q], gim[u][q]);
  }
}

// ---------------------------------------------------------------------------
// K5: S = x + C2R row inverse (33 bins) with ortho 1/128 scale.
// ---------------------------------------------------------------------------
__global__ __launch_bounds__(256) void k5_inv_w(const float* __restrict__ x) {
  __shared__ float gr[WFM*128], gi[WFM*128], twc[128], tws[128];
  int bc = blockIdx.x, tid = threadIdx.x;
  const float2* Gp = g_G + (size_t)bc*(WFM*HH);
  for (int idx = tid; idx < WFM*128; idx += 256) {
    float2 v = Gp[idx]; gr[idx]=v.x; gi[idx]=v.y;       // idx = wf*128 + h
  }
  if (tid < 128) { float s,c; sincospif((float)tid*(1.0f/64.0f),&s,&c); twc[tid]=c; tws[tid]=s; }
  __syncthreads();

  int w0 = (tid & 15) * 8, h0 = (tid >> 4) * 8;
  float e[8][8];
  #pragma unroll
  for (int u=0;u<8;++u) {
    #pragma unroll
    for (int v=0;v<8;++v) e[u][v]=0.f;
  }

  for (int k = 1; k < WFM; ++k) {
    float a[8], bv[8];
    #pragma unroll
    for (int u=0;u<8;++u){ a[u]=gr[k*128+h0+u]; bv[u]=gi[k*128+h0+u]; }
    #pragma unroll
    for (int v=0;v<8;++v) {
      int m = (k*(w0+v)) & 127;
      float c = twc[m], s = tws[m];
      #pragma unroll
      for (int u=0;u<8;++u) e[u][v] += a[u]*c - bv[u]*s;
    }
  }
  const float* xp = x + (size_t)bc*16384;
  float* Sp = g_S + (size_t)bc*16384;
  #pragma unroll
  for (int u=0;u<8;++u) {
    float g0 = (gr[h0+u] + BIN0_IM_W*gi[h0+u]) * (1.0f/128.0f);
    int row = (h0+u)*128 + w0;
    float4 x0 = *(const float4*)&xp[row];
    float4 x1 = *(const float4*)&xp[row+4];
    float4 r0, r1;
    r0.x = x0.x + g0 + e[u][0]*(1.0f/64.0f);
    r0.y = x0.y + g0 + e[u][1]*(1.0f/64.0f);
    r0.z = x0.z + g0 + e[u][2]*(1.0f/64.0f);
    r0.w = x0.w + g0 + e[u][3]*(1.0f/64.0f);
    r1.x = x1.x + g0 + e[u][4]*(1.0f/64.0f);
    r1.y = x1.y + g0 + e[u][5]*(1.0f/64.0f);
    r1.z = x1.z + g0 + e[u][6]*(1.0f/64.0f);
    r1.w = x1.w + g0 + e[u][7]*(1.0f/64.0f);
    *(float4*)&Sp[row]   = r0;
    *(float4*)&Sp[row+4] = r1;
  }
}

// ---------------------------------------------------------------------------
// K6: out[b,o,hw] = x[b,o,hw] + sum_c fw[o,c] * S[b,c,hw]
// ---------------------------------------------------------------------------
__global__ __launch_bounds__(256) void k6_fuse(const float* __restrict__ x,
                                              const float* __restrict__ fw,
                                              float* __restrict__ out) {
  __shared__ float ws[64*17];    // [o][c]
  __shared__ float ss[16*132];   // [c][hw]
  int bx = blockIdx.x;
  int hwT = (bx & 127) * 128;
  int t2 = bx >> 7;
  int oT = (t2 & 7) * 64;
  int b  = t2 >> 3;
  int tid = threadIdx.x;
  const float* Sb = g_S + (size_t)b*CC*16384;

  int o0 = (tid >> 5) * 8;
  int w0 = (tid & 31) * 4;
  float acc[8][4];
  #pragma unroll
  for (int u=0;u<8;++u) {
    #pragma unroll
    for (int v=0;v<4;++v) acc[u][v]=0.f;
  }

  for (int c0 = 0; c0 < 512; c0 += 16) {
    #pragma unroll
    for (int q=0;q<4;++q) {
      int idx = tid*4 + q;
      int o = idx >> 4, c = idx & 15;
      ws[o*17 + c] = fw[(size_t)(oT+o)*512 + c0 + c];
    }
    #pragma unroll
    for (int q=0;q<2;++q) {
      int idx = tid + q*256;            // 0..511 float4 slots
      int c = idx >> 5, cv = idx & 31;
      float4 v = *(const float4*)&Sb[(size_t)(c0+c)*16384 + hwT + cv*4];
      *(float4*)&ss[c*132 + cv*4] = v;
    }
    __syncthreads();
    #pragma unroll
    for (int kk=0;kk<16;++kk) {
      float4 s4 = *(float4*)&ss[kk*132 + w0];
      #pragma unroll
      for (int u=0;u<8;++u) {
        float wv = ws[(o0+u)*17 + kk];
        acc[u][0] += wv*s4.x; acc[u][1] += wv*s4.y;
        acc[u][2] += wv*s4.z; acc[u][3] += wv*s4.w;
      }
    }
    __syncthreads();
  }
  #pragma unroll
  for (int u=0;u<8;++u) {
    size_t ob = ((size_t)(b*512 + oT + o0 + u))*16384 + hwT + w0;
    float4 xv = *(const float4*)&x[ob];
    float4 r;
    r.x = xv.x + acc[u][0]; r.y = xv.y + acc[u][1];
    r.z = xv.z + acc[u][2]; r.w = xv.w + acc[u][3];
    *(float4*)&out[ob] = r;
  }
}

// ---------------------------------------------------------------------------
extern "C" void kernel_launch(void* const* d_in, const int* in_sizes, int n_in,
                              void* d_out, int out_size) {
  const float* x   = (const float*)d_in[0];
  const float* w1r = (const float*)d_in[1];
  const float* w1i = (const float*)d_in[2];
  const float* b1r = (const float*)d_in[3];
  const float* b1i = (const float*)d_in[4];
  const float* w2r = (const float*)d_in[5];
  const float* w2i = (const float*)d_in[6];
  const float* b2r = (const float*)d_in[7];
  const float* b2i = (const float*)d_in[8];
  const float* fw  = (const float*)d_in[9];
  float* out = (float*)d_out;

  cudaFuncSetAttribute(k1_fwd_w, cudaFuncAttributeMaxDynamicSharedMemorySize, 68608);
  cudaFuncSetAttribute(k2_fwd_h, cudaFuncAttributeMaxDynamicSharedMemorySize, 69120);
  cudaFuncSetAttribute(k3_mlp,   cudaFuncAttributeMaxDynamicSharedMemorySize, 100352);

  k1_fwd_w<<<BB*CC, 288, 68608>>>(x);
  k2_fwd_h<<<BB*NBK*WFM, 256, 69120>>>();
  k3_mlp<<<NBK*132, 256, 100352>>>(w1r, w1i, b1r, b1i, w2r, w2i, b2r, b2i);
  k4_inv_h<<<BB*NBK*WFM, 256>>>();
  k5_inv_w<<<BB*CC, 256>>>(x);
  k6_fuse<<<BB*8*128, 256>>>(x, fw, out);
}

// round 7
// speedup vs baseline: 1.5286x; 1.5286x over previous
#include <cuda_runtime.h>
#include <math.h>
#include <stdint.h>

#define BB   4
#define CC   512
#define NBK  8
#define BSZ  64
#define HH   128
#define WW   128
#define WFM  33
#define KHM  64
#define NPTS (BB*KHM*WFM)     // 8448

#define BIN0_IM_W 0.0f

// ------------------------- static device scratch ---------------------------
__device__ float2 g_F[BB*CC*WFM*HH];
__device__ float  g_Zr[NBK*NPTS*BSZ];
__device__ float  g_Zi[NBK*NPTS*BSZ];
__device__ float  g_Dr[NBK*NPTS*BSZ];
__device__ float  g_Di[NBK*NPTS*BSZ];
__device__ float2 g_G[BB*CC*WFM*HH];
__device__ float  g_S[BB*CC*HH*WW];

// ---------------------------------------------------------------------------
// K1: F[bc,wf,h] = sum_w x[bc,h,w] e^{-2pi i w wf/128}, wf<33
// ---------------------------------------------------------------------------
__global__ __launch_bounds__(288) void k1_fwd_w(const float* __restrict__ x) {
  extern __shared__ float sm1[];
  float* xs  = sm1;            // [128 w][132]
  float* twc = sm1 + 16896;
  float* tws = sm1 + 17024;
  int bc = blockIdx.x, tid = threadIdx.x;
  const float* xp = x + (size_t)bc * 16384;
  for (int idx = tid; idx < 16384; idx += 288) {
    int h = idx >> 7, w = idx & 127;
    xs[w*132 + h] = xp[idx];
  }
  if (tid < 128) { float s,c; sincospif((float)tid*(1.0f/64.0f),&s,&c); twc[tid]=c; tws[tid]=s; }
  __syncthreads();

  int wf0 = (tid >> 5) * 4;
  int h0  = (tid & 31) * 4;
  float fr[4][4], fi[4][4];
  #pragma unroll
  for (int j=0;j<4;++j) {
    #pragma unroll
    for (int u=0;u<4;++u){ fr[j][u]=0.f; fi[j][u]=0.f; }
  }

  for (int w = 0; w < 128; ++w) {
    float4 a4 = *(float4*)&xs[w*132 + h0];
    float a[4] = {a4.x, a4.y, a4.z, a4.w};
    #pragma unroll
    for (int j=0;j<4;++j) {
      int m = (w*(wf0+j)) & 127;
      float c = twc[m], s = tws[m];
      #pragma unroll
      for (int u=0;u<4;++u){ fr[j][u]+=a[u]*c; fi[j][u]-=a[u]*s; }
    }
  }
  float2* Fp = g_F + (size_t)bc*(WFM*HH);
  #pragma unroll
  for (int j=0;j<4;++j) {
    int wf = wf0+j;
    if (wf < WFM) {
      #pragma unroll
      for (int u=0;u<4;++u) Fp[wf*128 + h0+u] = make_float2(fr[j][u], fi[j][u]);
    }
  }
}

// ---------------------------------------------------------------------------
// K2: Z[k] = (1/128) sum_h F[h] e^{-2pi i h k/128}, k<64. block=(b,n,wf)
// ---------------------------------------------------------------------------
__global__ __launch_bounds__(256) void k2_fwd_h() {
  extern __shared__ float sm2[];
  float* fr  = sm2;              // [64 i][133]
  float* fi  = sm2 + 8512;
  float* twc = sm2 + 17024;
  float* tws = sm2 + 17152;
  int bx = blockIdx.x;
  int wfi = bx % 33; int t = bx / 33; int n = t & 7; int b = t >> 3;
  int tid = threadIdx.x;
  const float2* Fb = g_F + ((size_t)(b*CC + n*BSZ)*WFM + wfi)*HH;
  for (int idx = tid; idx < 8192; idx += 256) {
    int i = idx >> 7, h = idx & 127;
    float2 v = Fb[(size_t)i*(WFM*HH) + h];
    fr[i*133 + h] = v.x; fi[i*133 + h] = v.y;
  }
  if (tid < 128) { float s,c; sincospif((float)tid*(1.0f/64.0f),&s,&c); twc[tid]=c; tws[tid]=s; }
  __syncthreads();

  int i0 = (tid & 15) * 4, k0 = (tid >> 4) * 4;
  float zr[4][4], zi[4][4];
  #pragma unroll
  for (int kk=0;kk<4;++kk) {
    #pragma unroll
    for (int u=0;u<4;++u){ zr[kk][u]=0.f; zi[kk][u]=0.f; }
  }

  for (int h = 0; h < 128; ++h) {
    float ar[4], ai[4];
    #pragma unroll
    for (int u=0;u<4;++u){ ar[u]=fr[(i0+u)*133+h]; ai[u]=fi[(i0+u)*133+h]; }
    #pragma unroll
    for (int kk=0;kk<4;++kk) {
      int m = (h*(k0+kk)) & 127;
      float c = twc[m], s = tws[m];
      #pragma unroll
      for (int u=0;u<4;++u) {
        zr[kk][u] += ar[u]*c + ai[u]*s;
        zi[kk][u] += ai[u]*c - ar[u]*s;
      }
    }
  }
  const float sc = 1.0f/128.0f;
  #pragma unroll
  for (int kk=0;kk<4;++kk) {
    int p = (b*KHM + k0+kk)*WFM + wfi;
    size_t base = ((size_t)n*NPTS + p)*BSZ + i0;
    *(float4*)(g_Zr+base) = make_float4(zr[kk][0]*sc, zr[kk][1]*sc, zr[kk][2]*sc, zr[kk][3]*sc);
    *(float4*)(g_Zi+base) = make_float4(zi[kk][0]*sc, zi[kk][1]*sc, zi[kk][2]*sc, zi[kk][3]*sc);
  }
}

// ---------------------------------------------------------------------------
// K3: D = softshrink(W2 @ gelu(W1 @ z + b1) + b2) - z
// ---------------------------------------------------------------------------
__device__ __forceinline__ float gelu_f(float v) {
  return 0.5f*v*(1.0f + erff(v*0.70710678118654752f));
}
__device__ __forceinline__ float sshrink_f(float v) {
  float a = fabsf(v) - 0.01f;
  return a > 0.0f ? copysignf(a, v) : 0.0f;
}

__global__ __launch_bounds__(256) void k3_mlp(
    const float* __restrict__ w1r, const float* __restrict__ w1i,
    const float* __restrict__ b1r, const float* __restrict__ b1i,
    const float* __restrict__ w2r, const float* __restrict__ w2i,
    const float* __restrict__ b2r, const float* __restrict__ b2i) {
  extern __shared__ float sm3[];
  float* wsr = sm3;            float* wsi = sm3 + 4096;
  float* zsr = sm3 + 8192;     float* zsi = sm3 + 12352;
  float* hsr = sm3 + 16512;    float* hsi = sm3 + 20672;
  float* bs  = sm3 + 24832;
  int bx = blockIdx.x;
  int n = bx / 132, pt = bx % 132;
  int tid = threadIdx.x;
  size_t zbase = ((size_t)n*NPTS + (size_t)pt*64)*64;

  for (int idx = tid; idx < 4096; idx += 256) {
    int p = idx >> 6, i = idx & 63;
    wsr[idx] = w1r[n*4096 + idx]; wsi[idx] = w1i[n*4096 + idx];
    zsr[p*65+i] = g_Zr[zbase + idx]; zsi[p*65+i] = g_Zi[zbase + idx];
  }
  if (tid < 64) {
    bs[tid]     = b1r[n*64+tid]; bs[64+tid]  = b1i[n*64+tid];
    bs[128+tid] = b2r[n*64+tid]; bs[192+tid] = b2i[n*64+tid];
  }
  __syncthreads();

  int j0 = (tid & 15) * 4, p0 = (tid >> 4) * 4;
  float hr[4][4], hi2[4][4];
  #pragma unroll
  for (int u=0;u<4;++u) {
    #pragma unroll
    for (int v=0;v<4;++v){ hr[u][v]=bs[j0+v]; hi2[u][v]=bs[64+j0+v]; }
  }

  for (int i = 0; i < 64; ++i) {
    float zr[4], zi2[4], wr[4], wi2[4];
    #pragma unroll
    for (int u=0;u<4;++u){ zr[u]=zsr[(p0+u)*65+i]; zi2[u]=zsi[(p0+u)*65+i]; }
    float4 w4r = *(float4*)&wsr[i*64+j0];
    float4 w4i = *(float4*)&wsi[i*64+j0];
    wr[0]=w4r.x; wr[1]=w4r.y; wr[2]=w4r.z; wr[3]=w4r.w;
    wi2[0]=w4i.x; wi2[1]=w4i.y; wi2[2]=w4i.z; wi2[3]=w4i.w;
    #pragma unroll
    for (int u=0;u<4;++u) {
      #pragma unroll
      for (int v=0;v<4;++v){
        hr[u][v]  += zr[u]*wr[v]  - zi2[u]*wi2[v];
        hi2[u][v] += zr[u]*wi2[v] + zi2[u]*wr[v];
      }
    }
  }
  #pragma unroll
  for (int u=0;u<4;++u) {
    #pragma unroll
    for (int v=0;v<4;++v){
      hsr[(p0+u)*65 + j0+v] = gelu_f(hr[u][v]);
      hsi[(p0+u)*65 + j0+v] = gelu_f(hi2[u][v]);
    }
  }
  __syncthreads();
  for (int idx = tid; idx < 4096; idx += 256) {
    wsr[idx] = w2r[n*4096 + idx]; wsi[idx] = w2i[n*4096 + idx];
  }
  __syncthreads();

  float yr[4][4], yi[4][4];
  #pragma unroll
  for (int u=0;u<4;++u) {
    #pragma unroll
    for (int v=0;v<4;++v){ yr[u][v]=bs[128+j0+v]; yi[u][v]=bs[192+j0+v]; }
  }

  for (int i = 0; i < 64; ++i) {
    float ar[4], ai[4], wr[4], wi2[4];
    #pragma unroll
    for (int u=0;u<4;++u){ ar[u]=hsr[(p0+u)*65+i]; ai[u]=hsi[(p0+u)*65+i]; }
    float4 w4r = *(float4*)&wsr[i*64+j0];
    float4 w4i = *(float4*)&wsi[i*64+j0];
    wr[0]=w4r.x; wr[1]=w4r.y; wr[2]=w4r.z; wr[3]=w4r.w;
    wi2[0]=w4i.x; wi2[1]=w4i.y; wi2[2]=w4i.z; wi2[3]=w4i.w;
    #pragma unroll
    for (int u=0;u<4;++u) {
      #pragma unroll
      for (int v=0;v<4;++v){
        yr[u][v] += ar[u]*wr[v]  - ai[u]*wi2[v];
        yi[u][v] += ar[u]*wi2[v] + ai[u]*wr[v];
      }
    }
  }
  #pragma unroll
  for (int u=0;u<4;++u) {
    float4 dr, di;
    dr.x = sshrink_f(yr[u][0]) - zsr[(p0+u)*65 + j0+0];
    dr.y = sshrink_f(yr[u][1]) - zsr[(p0+u)*65 + j0+1];
    dr.z = sshrink_f(yr[u][2]) - zsr[(p0+u)*65 + j0+2];
    dr.w = sshrink_f(yr[u][3]) - zsr[(p0+u)*65 + j0+3];
    di.x = sshrink_f(yi[u][0]) - zsi[(p0+u)*65 + j0+0];
    di.y = sshrink_f(yi[u][1]) - zsi[(p0+u)*65 + j0+1];
    di.z = sshrink_f(yi[u][2]) - zsi[(p0+u)*65 + j0+2];
    di.w = sshrink_f(yi[u][3]) - zsi[(p0+u)*65 + j0+3];
    size_t ob = zbase + (size_t)(p0+u)*64 + j0;
    *(float4*)(g_Dr+ob) = dr;
    *(float4*)(g_Di+ob) = di;
  }
}

// ---------------------------------------------------------------------------
// K4: G[h] = sum_{k<64} D[k] e^{+2pi i h k/128}
// ---------------------------------------------------------------------------
__global__ __launch_bounds__(256) void k4_inv_h() {
  __shared__ float dsr[4096], dsi[4096], twc[128], tws[128];
  int bx = blockIdx.x;
  int wfi = bx % 33; int t = bx / 33; int n = t & 7; int b = t >> 3;
  int tid = threadIdx.x;
  size_t base = ((size_t)n*NPTS + (size_t)(b*KHM)*WFM + wfi)*64;
  for (int idx = tid; idx < 4096; idx += 256) {
    int k = idx >> 6, i = idx & 63;
    dsr[idx] = g_Dr[base + (size_t)k*(WFM*64) + i];
    dsi[idx] = g_Di[base + (size_t)k*(WFM*64) + i];
  }
  if (tid < 128) { float s,c; sincospif((float)tid*(1.0f/64.0f),&s,&c); twc[tid]=c; tws[tid]=s; }
  __syncthreads();

  int h0 = (tid & 15) * 8, i0 = (tid >> 4) * 4;
  float gre[4][8], gim[4][8];
  #pragma unroll
  for (int u=0;u<4;++u) {
    #pragma unroll
    for (int q=0;q<8;++q){ gre[u][q]=0.f; gim[u][q]=0.f; }
  }

  for (int k = 0; k < 64; ++k) {
    float4 r4 = *(float4*)&dsr[k*64 + i0];
    float4 i4 = *(float4*)&dsi[k*64 + i0];
    float dr[4]={r4.x,r4.y,r4.z,r4.w}, di[4]={i4.x,i4.y,i4.z,i4.w};
    #pragma unroll
    for (int q=0;q<8;++q) {
      int m = ((h0+q)*k) & 127;
      float c = twc[m], s = tws[m];
      #pragma unroll
      for (int u=0;u<4;++u) {
        gre[u][q] += dr[u]*c - di[u]*s;
        gim[u][q] += dr[u]*s + di[u]*c;
      }
    }
  }
  #pragma unroll
  for (int u=0;u<4;++u) {
    float2* Gp = g_G + ((size_t)(b*CC + n*BSZ + i0+u)*WFM + wfi)*HH + h0;
    #pragma unroll
    for (int q=0;q<8;++q) Gp[q] = make_float2(gre[u][q], gim[u][q]);
  }
}

// ---------------------------------------------------------------------------
// K5: S = x + C2R row inverse (33 bins), ortho scale.
// ---------------------------------------------------------------------------
__global__ __launch_bounds__(256) void k5_inv_w(const float* __restrict__ x) {
  __shared__ float gr[WFM*128], gi[WFM*128], twc[128], tws[128];
  int bc = blockIdx.x, tid = threadIdx.x;
  const float2* Gp = g_G + (size_t)bc*(WFM*HH);
  for (int idx = tid; idx < WFM*128; idx += 256) {
    float2 v = Gp[idx]; gr[idx]=v.x; gi[idx]=v.y;
  }
  if (tid < 128) { float s,c; sincospif((float)tid*(1.0f/64.0f),&s,&c); twc[tid]=c; tws[tid]=s; }
  __syncthreads();

  int w0 = (tid & 15) * 8, h0 = (tid >> 4) * 8;
  float e[8][8];
  #pragma unroll
  for (int u=0;u<8;++u) {
    #pragma unroll
    for (int v=0;v<8;++v) e[u][v]=0.f;
  }

  for (int k = 1; k < WFM; ++k) {
    float a[8], bv[8];
    #pragma unroll
    for (int u=0;u<8;++u){ a[u]=gr[k*128+h0+u]; bv[u]=gi[k*128+h0+u]; }
    #pragma unroll
    for (int v=0;v<8;++v) {
      int m = (k*(w0+v)) & 127;
      float c = twc[m], s = tws[m];
      #pragma unroll
      for (int u=0;u<8;++u) e[u][v] += a[u]*c - bv[u]*s;
    }
  }
  const float* xp = x + (size_t)bc*16384;
  float* Sp = g_S + (size_t)bc*16384;
  #pragma unroll
  for (int u=0;u<8;++u) {
    float g0 = (gr[h0+u] + BIN0_IM_W*gi[h0+u]) * (1.0f/128.0f);
    int row = (h0+u)*128 + w0;
    float4 x0 = *(const float4*)&xp[row];
    float4 x1 = *(const float4*)&xp[row+4];
    float4 r0, r1;
    r0.x = x0.x + g0 + e[u][0]*(1.0f/64.0f);
    r0.y = x0.y + g0 + e[u][1]*(1.0f/64.0f);
    r0.z = x0.z + g0 + e[u][2]*(1.0f/64.0f);
    r0.w = x0.w + g0 + e[u][3]*(1.0f/64.0f);
    r1.x = x1.x + g0 + e[u][4]*(1.0f/64.0f);
    r1.y = x1.y + g0 + e[u][5]*(1.0f/64.0f);
    r1.z = x1.z + g0 + e[u][6]*(1.0f/64.0f);
    r1.w = x1.w + g0 + e[u][7]*(1.0f/64.0f);
    *(float4*)&Sp[row]   = r0;
    *(float4*)&Sp[row+4] = r1;
  }
}

// ---------------------------------------------------------------------------
// K6 (mma.sync TF32): out[b,o,hw] = x[b,o,hw] + sum_c fw[o,c] * S[b,c,hw]
// CTA: 128(o) x 128(hw), K=512 in 32 chunks of 16. 8 warps: 4(M) x 2(N),
// each warp 32x64 via m16n8k8 tf32 fragments from padded smem.
// ---------------------------------------------------------------------------
#define AS_STRIDE 20     // conflict-free for quad fragment loads
#define BS_STRIDE 136

__device__ __forceinline__ uint32_t f2tf32(float f) {
  uint32_t r; asm("cvt.rna.tf32.f32 %0, %1;" : "=r"(r) : "f"(f)); return r;
}
__device__ __forceinline__ void mma1688(float* d, const uint32_t* a, const uint32_t* b2) {
  asm volatile(
    "mma.sync.aligned.m16n8k8.row.col.f32.tf32.tf32.f32 "
    "{%0,%1,%2,%3}, {%4,%5,%6,%7}, {%8,%9}, {%0,%1,%2,%3};"
    : "+f"(d[0]), "+f"(d[1]), "+f"(d[2]), "+f"(d[3])
    : "r"(a[0]), "r"(a[1]), "r"(a[2]), "r"(a[3]), "r"(b2[0]), "r"(b2[1]));
}

__global__ __launch_bounds__(256) void k6_fuse_mma(const float* __restrict__ x,
                                                   const float* __restrict__ fw,
                                                   float* __restrict__ out) {
  __shared__ uint32_t As[128*AS_STRIDE];   // [o][k] tf32
  __shared__ uint32_t Bs[16*BS_STRIDE];    // [k][hw] tf32
  int tid = threadIdx.x;
  int lane = tid & 31, wid = tid >> 5;
  int bx = blockIdx.x;
  int hwT = (bx & 127) * 128;
  int t2 = bx >> 7;
  int oT = (t2 & 3) * 128;
  int b  = t2 >> 2;
  const float* Sb = g_S + (size_t)b*CC*16384;

  int wm = (wid & 3) * 32;     // warp M offset in tile
  int wn = (wid >> 2) * 64;    // warp N offset in tile
  int qr = lane >> 2;          // 0..7 row-in-group
  int qc = lane & 3;           // 0..3 col-in-group

  float acc[2][8][4];
  #pragma unroll
  for (int mt=0;mt<2;++mt) {
    #pragma unroll
    for (int nt=0;nt<8;++nt) {
      #pragma unroll
      for (int r=0;r<4;++r) acc[mt][nt][r]=0.f;
    }
  }

  for (int ch = 0; ch < 32; ++ch) {
    int c0 = ch * 16;
    // load A: fw[oT..+127][c0..+15] -> As[o][k]
    #pragma unroll
    for (int it = 0; it < 2; ++it) {
      int slot = it*256 + tid;          // 512 float4 slots
      int o = slot >> 2, k4 = slot & 3;
      float4 v = *(const float4*)&fw[(size_t)(oT+o)*512 + c0 + k4*4];
      uint32_t* dst = &As[o*AS_STRIDE + k4*4];
      dst[0]=f2tf32(v.x); dst[1]=f2tf32(v.y); dst[2]=f2tf32(v.z); dst[3]=f2tf32(v.w);
    }
    // load B: S[c0..+15][hwT..+127] -> Bs[k][hw]
    #pragma unroll
    for (int it = 0; it < 2; ++it) {
      int slot = it*256 + tid;          // 512 float4 slots
      int k = slot >> 5, h4 = slot & 31;
      float4 v = *(const float4*)&Sb[(size_t)(c0+k)*16384 + hwT + h4*4];
      uint32_t* dst = &Bs[k*BS_STRIDE + h4*4];
      dst[0]=f2tf32(v.x); dst[1]=f2tf32(v.y); dst[2]=f2tf32(v.z); dst[3]=f2tf32(v.w);
    }
    __syncthreads();

    #pragma unroll
    for (int ks = 0; ks < 16; ks += 8) {
      uint32_t afr[2][4];
      #pragma unroll
      for (int mt=0;mt<2;++mt) {
        int rb = wm + mt*16;
        afr[mt][0] = As[(rb + qr     )*AS_STRIDE + ks + qc    ];
        afr[mt][1] = As[(rb + qr + 8 )*AS_STRIDE + ks + qc    ];
        afr[mt][2] = As[(rb + qr     )*AS_STRIDE + ks + qc + 4];
        afr[mt][3] = As[(rb + qr + 8 )*AS_STRIDE + ks + qc + 4];
      }
      #pragma unroll
      for (int nt=0;nt<8;++nt) {
        int cb = wn + nt*8;
        uint32_t bfr[2];
        bfr[0] = Bs[(ks + qc    )*BS_STRIDE + cb + qr];
        bfr[1] = Bs[(ks + qc + 4)*BS_STRIDE + cb + qr];
        mma1688(acc[0][nt], afr[0], bfr);
        mma1688(acc[1][nt], afr[1], bfr);
      }
    }
    __syncthreads();
  }

  // epilogue: add x, store
  #pragma unroll
  for (int mt=0;mt<2;++mt) {
    int row0 = oT + wm + mt*16 + qr;
    #pragma unroll
    for (int nt=0;nt<8;++nt) {
      int col = hwT + wn + nt*8 + qc*2;
      size_t ob0 = ((size_t)(b*512 + row0    ))*16384 + col;
      size_t ob1 = ((size_t)(b*512 + row0 + 8))*16384 + col;
      float2 x0 = *(const float2*)&x[ob0];
      float2 x1 = *(const float2*)&x[ob1];
      float2 r0, r1;
      r0.x = x0.x + acc[mt][nt][0]; r0.y = x0.y + acc[mt][nt][1];
      r1.x = x1.x + acc[mt][nt][2]; r1.y = x1.y + acc[mt][nt][3];
      *(float2*)&out[ob0] = r0;
      *(float2*)&out[ob1] = r1;
    }
  }
}

// ---------------------------------------------------------------------------
extern "C" void kernel_launch(void* const* d_in, const int* in_sizes, int n_in,
                              void* d_out, int out_size) {
  const float* x   = (const float*)d_in[0];
  const float* w1r = (const float*)d_in[1];
  const float* w1i = (const float*)d_in[2];
  const float* b1r = (const float*)d_in[3];
  const float* b1i = (const float*)d_in[4];
  const float* w2r = (const float*)d_in[5];
  const float* w2i = (const float*)d_in[6];
  const float* b2r = (const float*)d_in[7];
  const float* b2i = (const float*)d_in[8];
  const float* fw  = (const float*)d_in[9];
  float* out = (float*)d_out;

  cudaFuncSetAttribute(k1_fwd_w, cudaFuncAttributeMaxDynamicSharedMemorySize, 68608);
  cudaFuncSetAttribute(k2_fwd_h, cudaFuncAttributeMaxDynamicSharedMemorySize, 69120);
  cudaFuncSetAttribute(k3_mlp,   cudaFuncAttributeMaxDynamicSharedMemorySize, 100352);

  k1_fwd_w<<<BB*CC, 288, 68608>>>(x);
  k2_fwd_h<<<BB*NBK*WFM, 256, 69120>>>();
  k3_mlp<<<NBK*132, 256, 100352>>>(w1r, w1i, b1r, b1i, w2r, w2i, b2r, b2i);
  k4_inv_h<<<BB*NBK*WFM, 256>>>();
  k5_inv_w<<<BB*CC, 256>>>(x);
  k6_fuse_mma<<<BB*4*128, 256>>>(x, fw, out);
}

// round 9
// speedup vs baseline: 2.0757x; 1.3579x over previous
#include <cuda_runtime.h>
#include <math.h>
#include <stdint.h>

#define BB   4
#define CC   512
#define NBK  8
#define BSZ  64
#define WFM  33
#define KHM  64
#define NPTS (BB*KHM*WFM)     // 8448

// ------------------------- static device scratch ---------------------------
__device__ float  g_Zr[NBK*NPTS*BSZ];
__device__ float  g_Zi[NBK*NPTS*BSZ];
__device__ float  g_Dr[NBK*NPTS*BSZ];
__device__ float  g_Di[NBK*NPTS*BSZ];
__device__ float  g_S[BB*CC*128*128];

// twiddle tables (tf32 bit patterns)
__device__ uint32_t T1g[128*72];    // [w][nf]: cos | -sin | 0
__device__ uint32_t T2g[128*128];   // [m][h]: m<64 cos(hk), else sin(hk)
__device__ uint32_t T3g[128*128];   // [h][kk]: kk<64 cos(h k), else sin
__device__ uint32_t T4g[72*136];    // [kk][w]: C2R coeffs with 1/128 folded

__device__ __forceinline__ uint32_t f2tf32(float f) {
  uint32_t r; asm("cvt.rna.tf32.f32 %0, %1;" : "=r"(r) : "f"(f)); return r;
}
__device__ __forceinline__ void mma1688(float* d, const uint32_t* a, const uint32_t* b2) {
  asm volatile(
    "mma.sync.aligned.m16n8k8.row.col.f32.tf32.tf32.f32 "
    "{%0,%1,%2,%3}, {%4,%5,%6,%7}, {%8,%9}, {%0,%1,%2,%3};"
    : "+f"(d[0]), "+f"(d[1]), "+f"(d[2]), "+f"(d[3])
    : "r"(a[0]), "r"(a[1]), "r"(a[2]), "r"(a[3]), "r"(b2[0]), "r"(b2[1]));
}

// ---------------------------------------------------------------------------
// K0: build twiddle tables (tf32). Cheap; runs every launch (deterministic).
// ---------------------------------------------------------------------------
__global__ __launch_bounds__(256) void k0_twiddle() {
  int tid = blockIdx.x*256 + threadIdx.x;
  for (int idx = tid; idx < 128*72; idx += 256*32) {
    int w = idx / 72, nf = idx % 72;
    float v = 0.f;
    if (nf < 33)      v =  cospif((float)((w*nf) & 127) * (1.0f/64.0f));
    else if (nf < 66) v = -sinpif((float)((w*(nf-33)) & 127) * (1.0f/64.0f));
    T1g[idx] = f2tf32(v);
  }
  for (int idx = tid; idx < 128*128; idx += 256*32) {
    int m = idx >> 7, h = idx & 127;
    float v = (m < 64) ? cospif((float)((h*m) & 127) * (1.0f/64.0f))
                       : sinpif((float)((h*(m-64)) & 127) * (1.0f/64.0f));
    T2g[idx] = f2tf32(v);
  }
  for (int idx = tid; idx < 128*128; idx += 256*32) {
    int h = idx >> 7, kk = idx & 127;
    float v = (kk < 64) ? cospif((float)((h*kk) & 127) * (1.0f/64.0f))
                        : sinpif((float)((h*(kk-64)) & 127) * (1.0f/64.0f));
    T3g[idx] = f2tf32(v);
  }
  for (int idx = tid; idx < 72*136; idx += 256*32) {
    int kk = idx / 136, w = idx % 136;
    float v = 0.f;
    if (w < 128) {
      if (kk == 0)       v = 1.0f/128.0f;
      else if (kk < 33)  v =  (1.0f/64.0f) * cospif((float)((w*kk) & 127) * (1.0f/64.0f));
      else if (kk == 33) v = 0.f;   // bin-0 imag discarded (pocketfft C2R)
      else if (kk < 66)  v = -(1.0f/64.0f) * sinpif((float)((w*(kk-33)) & 127) * (1.0f/64.0f));
    }
    T4g[idx] = f2tf32(v);
  }
}

// ---------------------------------------------------------------------------
// K12: fused forward. Per (b,c) image:
//   GEMM1: O1[h][nf] = x[h][w] @ T1[w][nf]           (M=128,N=72,K=128)
//   GEMM2: O2[m][nf] = T2[m][h] @ O1^T-as-B[h][nf]   (M=128,N=72,K=128)
//   Zr = (O2[k][wf] + O2[64+k][33+wf])/128 ; Zi = (O2[k][33+wf] - O2[64+k][wf])/128
// ---------------------------------------------------------------------------
__global__ __launch_bounds__(256) void k12_fwd(const float* __restrict__ x) {
  extern __shared__ uint32_t smw[];
  uint32_t* As = smw;            // [128][36] chunked A
  uint32_t* B1 = smw + 4608;     // [128][72] T1, later O2 staging (fp32)
  uint32_t* B2 = smw + 13824;    // [128][72] F = GEMM1 output (tf32)
  float* O2f = (float*)B1;

  int tid = threadIdx.x;
  int lane = tid & 31, wid = tid >> 5;
  int qr = lane >> 2, qc = lane & 3;
  int m0 = wid * 16;
  int bc = blockIdx.x;
  int b = bc >> 9, c = bc & 511;
  const float* xp = x + (size_t)bc * 16384;

  for (int i = tid; i < 9216; i += 256) B1[i] = T1g[i];

  // ---- GEMM1 ----
  float acc[9][4];
  #pragma unroll
  for (int nt=0;nt<9;++nt) {
    #pragma unroll
    for (int r=0;r<4;++r) acc[nt][r]=0.f;
  }
  for (int kc = 0; kc < 128; kc += 32) {
    __syncthreads();
    #pragma unroll
    for (int it = 0; it < 16; ++it) {
      int s = it*256 + tid;
      int h = s >> 5, w = s & 31;
      As[h*36 + w] = f2tf32(xp[h*128 + kc + w]);
    }
    __syncthreads();
    #pragma unroll
    for (int ks = 0; ks < 4; ++ks) {
      int k8 = ks*8;
      uint32_t a[4];
      a[0] = As[(m0+qr  )*36 + k8+qc  ];
      a[1] = As[(m0+qr+8)*36 + k8+qc  ];
      a[2] = As[(m0+qr  )*36 + k8+qc+4];
      a[3] = As[(m0+qr+8)*36 + k8+qc+4];
      #pragma unroll
      for (int nt=0;nt<9;++nt) {
        uint32_t bfr[2];
        bfr[0] = B1[(kc+k8+qc  )*72 + nt*8+qr];
        bfr[1] = B1[(kc+k8+qc+4)*72 + nt*8+qr];
        mma1688(acc[nt], a, bfr);
      }
    }
  }
  __syncthreads();
  // store F (tf32) into B2 [h][nf]
  #pragma unroll
  for (int nt=0;nt<9;++nt) {
    int col = nt*8 + qc*2;
    B2[(m0+qr  )*72 + col  ] = f2tf32(acc[nt][0]);
    B2[(m0+qr  )*72 + col+1] = f2tf32(acc[nt][1]);
    B2[(m0+qr+8)*72 + col  ] = f2tf32(acc[nt][2]);
    B2[(m0+qr+8)*72 + col+1] = f2tf32(acc[nt][3]);
  }

  // ---- GEMM2 ----
  #pragma unroll
  for (int nt=0;nt<9;++nt) {
    #pragma unroll
    for (int r=0;r<4;++r) acc[nt][r]=0.f;
  }
  for (int kc = 0; kc < 128; kc += 32) {
    __syncthreads();
    #pragma unroll
    for (int it = 0; it < 16; ++it) {
      int s = it*256 + tid;
      int m = s >> 5, h = s & 31;
      As[m*36 + h] = T2g[m*128 + kc + h];
    }
    __syncthreads();
    #pragma unroll
    for (int ks = 0; ks < 4; ++ks) {
      int k8 = ks*8;
      uint32_t a[4];
      a[0] = As[(m0+qr  )*36 + k8+qc  ];
      a[1] = As[(m0+qr+8)*36 + k8+qc  ];
      a[2] = As[(m0+qr  )*36 + k8+qc+4];
      a[3] = As[(m0+qr+8)*36 + k8+qc+4];
      #pragma unroll
      for (int nt=0;nt<9;++nt) {
        uint32_t bfr[2];
        bfr[0] = B2[(kc+k8+qc  )*72 + nt*8+qr];
        bfr[1] = B2[(kc+k8+qc+4)*72 + nt*8+qr];
        mma1688(acc[nt], a, bfr);
      }
    }
  }
  __syncthreads();
  #pragma unroll
  for (int nt=0;nt<9;++nt) {
    int col = nt*8 + qc*2;
    O2f[(m0+qr  )*72 + col  ] = acc[nt][0];
    O2f[(m0+qr  )*72 + col+1] = acc[nt][1];
    O2f[(m0+qr+8)*72 + col  ] = acc[nt][2];
    O2f[(m0+qr+8)*72 + col+1] = acc[nt][3];
  }
  __syncthreads();

  int n = c >> 6, i = c & 63;
  for (int idx = tid; idx < 2112; idx += 256) {
    int k = idx / 33, wf = idx % 33;
    float zr = (O2f[k*72 + wf] + O2f[(64+k)*72 + 33+wf]) * 0.0078125f;
    float zi = (O2f[k*72 + 33+wf] - O2f[(64+k)*72 + wf]) * 0.0078125f;
    size_t base = ((size_t)n*NPTS + ((size_t)(b*64+k)*33 + wf))*64 + i;
    g_Zr[base] = zr;
    g_Zi[base] = zi;
  }
}

// ---------------------------------------------------------------------------
// K3: D = softshrink(W2 @ gelu(W1 @ z + b1) + b2) - z   (unchanged fp32)
// ---------------------------------------------------------------------------
__device__ __forceinline__ float gelu_f(float v) {
  return 0.5f*v*(1.0f + erff(v*0.70710678118654752f));
}
__device__ __forceinline__ float sshrink_f(float v) {
  float a = fabsf(v) - 0.01f;
  return a > 0.0f ? copysignf(a, v) : 0.0f;
}

__global__ __launch_bounds__(256) void k3_mlp(
    const float* __restrict__ w1r, const float* __restrict__ w1i,
    const float* __restrict__ b1r, const float* __restrict__ b1i,
    const float* __restrict__ w2r, const float* __restrict__ w2i,
    const float* __restrict__ b2r, const float* __restrict__ b2i) {
  extern __shared__ float sm3[];
  float* wsr = sm3;            float* wsi = sm3 + 4096;
  float* zsr = sm3 + 8192;     float* zsi = sm3 + 12352;
  float* hsr = sm3 + 16512;    float* hsi = sm3 + 20672;
  float* bs  = sm3 + 24832;
  int bx = blockIdx.x;
  int n = bx / 132, pt = bx % 132;
  int tid = threadIdx.x;
  size_t zbase = ((size_t)n*NPTS + (size_t)pt*64)*64;

  for (int idx = tid; idx < 4096; idx += 256) {
    int p = idx >> 6, i = idx & 63;
    wsr[idx] = w1r[n*4096 + idx]; wsi[idx] = w1i[n*4096 + idx];
    zsr[p*65+i] = g_Zr[zbase + idx]; zsi[p*65+i] = g_Zi[zbase + idx];
  }
  if (tid < 64) {
    bs[tid]     = b1r[n*64+tid]; bs[64+tid]  = b1i[n*64+tid];
    bs[128+tid] = b2r[n*64+tid]; bs[192+tid] = b2i[n*64+tid];
  }
  __syncthreads();

  int j0 = (tid & 15) * 4, p0 = (tid >> 4) * 4;
  float hr[4][4], hi2[4][4];
  #pragma unroll
  for (int u=0;u<4;++u) {
    #pragma unroll
    for (int v=0;v<4;++v){ hr[u][v]=bs[j0+v]; hi2[u][v]=bs[64+j0+v]; }
  }

  for (int i = 0; i < 64; ++i) {
    float zr[4], zi2[4], wr[4], wi2[4];
    #pragma unroll
    for (int u=0;u<4;++u){ zr[u]=zsr[(p0+u)*65+i]; zi2[u]=zsi[(p0+u)*65+i]; }
    float4 w4r = *(float4*)&wsr[i*64+j0];
    float4 w4i = *(float4*)&wsi[i*64+j0];
    wr[0]=w4r.x; wr[1]=w4r.y; wr[2]=w4r.z; wr[3]=w4r.w;
    wi2[0]=w4i.x; wi2[1]=w4i.y; wi2[2]=w4i.z; wi2[3]=w4i.w;
    #pragma unroll
    for (int u=0;u<4;++u) {
      #pragma unroll
      for (int v=0;v<4;++v){
        hr[u][v]  += zr[u]*wr[v]  - zi2[u]*wi2[v];
        hi2[u][v] += zr[u]*wi2[v] + zi2[u]*wr[v];
      }
    }
  }
  #pragma unroll
  for (int u=0;u<4;++u) {
    #pragma unroll
    for (int v=0;v<4;++v){
      hsr[(p0+u)*65 + j0+v] = gelu_f(hr[u][v]);
      hsi[(p0+u)*65 + j0+v] = gelu_f(hi2[u][v]);
    }
  }
  __syncthreads();
  for (int idx = tid; idx < 4096; idx += 256) {
    wsr[idx] = w2r[n*4096 + idx]; wsi[idx] = w2i[n*4096 + idx];
  }
  __syncthreads();

  float yr[4][4], yi[4][4];
  #pragma unroll
  for (int u=0;u<4;++u) {
    #pragma unroll
    for (int v=0;v<4;++v){ yr[u][v]=bs[128+j0+v]; yi[u][v]=bs[192+j0+v]; }
  }

  for (int i = 0; i < 64; ++i) {
    float ar[4], ai[4], wr[4], wi2[4];
    #pragma unroll
    for (int u=0;u<4;++u){ ar[u]=hsr[(p0+u)*65+i]; ai[u]=hsi[(p0+u)*65+i]; }
    float4 w4r = *(float4*)&wsr[i*64+j0];
    float4 w4i = *(float4*)&wsi[i*64+j0];
    wr[0]=w4r.x; wr[1]=w4r.y; wr[2]=w4r.z; wr[3]=w4r.w;
    wi2[0]=w4i.x; wi2[1]=w4i.y; wi2[2]=w4i.z; wi2[3]=w4i.w;
    #pragma unroll
    for (int u=0;u<4;++u) {
      #pragma unroll
      for (int v=0;v<4;++v){
        yr[u][v] += ar[u]*wr[v]  - ai[u]*wi2[v];
        yi[u][v] += ar[u]*wi2[v] + ai[u]*wr[v];
      }
    }
  }
  #pragma unroll
  for (int u=0;u<4;++u) {
    float4 dr, di;
    dr.x = sshrink_f(yr[u][0]) - zsr[(p0+u)*65 + j0+0];
    dr.y = sshrink_f(yr[u][1]) - zsr[(p0+u)*65 + j0+1];
    dr.z = sshrink_f(yr[u][2]) - zsr[(p0+u)*65 + j0+2];
    dr.w = sshrink_f(yr[u][3]) - zsr[(p0+u)*65 + j0+3];
    di.x = sshrink_f(yi[u][0]) - zsi[(p0+u)*65 + j0+0];
    di.y = sshrink_f(yi[u][1]) - zsi[(p0+u)*65 + j0+1];
    di.z = sshrink_f(yi[u][2]) - zsi[(p0+u)*65 + j0+2];
    di.w = sshrink_f(yi[u][3]) - zsi[(p0+u)*65 + j0+3];
    size_t ob = zbase + (size_t)(p0+u)*64 + j0;
    *(float4*)(g_Dr+ob) = dr;
    *(float4*)(g_Di+ob) = di;
  }
}

// ---------------------------------------------------------------------------
// K45: fused inverse. Per (b,c) image:
//   B3 stacking: [Dr;-Di | Di;Dr] so GEMM3 O3[h][0..32]=Gr, [33..65]=Gi
//   GEMM3: O3 = T3[h][kk] @ B3[kk][nf]   (M=128,N=72,K=128)
//   GEMM4: S' = O3-as-A[h][kk] @ T4[kk][w] (M=128,N=128,K=72), S = x + S'
// ---------------------------------------------------------------------------
__global__ __launch_bounds__(256) void k45_inv(const float* __restrict__ x) {
  extern __shared__ uint32_t smw[];
  uint32_t* As  = smw;            // [128][36] chunked A (T3)
  uint32_t* R   = smw + 4608;     // B3 [128][72] then As4 [128][76]
  uint32_t* B4  = smw + 14336;    // [72][136] T4

  int tid = threadIdx.x;
  int lane = tid & 31, wid = tid >> 5;
  int qr = lane >> 2, qc = lane & 3;
  int m0 = wid * 16;
  int bc = blockIdx.x;
  int b = bc >> 9, c = bc & 511;
  int n = c >> 6, i = c & 63;

  for (int idx = tid; idx < 9792; idx += 256) B4[idx] = T4g[idx];

  // gather D -> B3 [kk][72]
  for (int idx = tid; idx < 2112; idx += 256) {
    int k = idx / 33, wf = idx % 33;
    size_t base = ((size_t)n*NPTS + ((size_t)(b*64+k)*33 + wf))*64 + i;
    float dr = g_Dr[base], di = g_Di[base];
    R[(k   )*72 + wf   ] = f2tf32(dr);
    R[(64+k)*72 + wf   ] = f2tf32(-di);
    R[(k   )*72 + 33+wf] = f2tf32(di);
    R[(64+k)*72 + 33+wf] = f2tf32(dr);
  }
  for (int idx = tid; idx < 128*6; idx += 256) {
    R[(idx/6)*72 + 66 + (idx % 6)] = 0u;
  }

  // ---- GEMM3 ----
  float acc3[9][4];
  #pragma unroll
  for (int nt=0;nt<9;++nt) {
    #pragma unroll
    for (int r=0;r<4;++r) acc3[nt][r]=0.f;
  }
  for (int kc = 0; kc < 128; kc += 32) {
    __syncthreads();
    #pragma unroll
    for (int it = 0; it < 16; ++it) {
      int s = it*256 + tid;
      int h = s >> 5, kl = s & 31;
      As[h*36 + kl] = T3g[h*128 + kc + kl];
    }
    __syncthreads();
    #pragma unroll
    for (int ks = 0; ks < 4; ++ks) {
      int k8 = ks*8;
      uint32_t a[4];
      a[0] = As[(m0+qr  )*36 + k8+qc  ];
      a[1] = As[(m0+qr+8)*36 + k8+qc  ];
      a[2] = As[(m0+qr  )*36 + k8+qc+4];
      a[3] = As[(m0+qr+8)*36 + k8+qc+4];
      #pragma unroll
      for (int nt=0;nt<9;++nt) {
        uint32_t bfr[2];
        bfr[0] = R[(kc+k8+qc  )*72 + nt*8+qr];
        bfr[1] = R[(kc+k8+qc+4)*72 + nt*8+qr];
        mma1688(acc3[nt], a, bfr);
      }
    }
  }
  __syncthreads();
  // store G (tf32) -> As4 [h][76] over B3 region (cols 66..71 are zeros by construction)
  #pragma unroll
  for (int nt=0;nt<9;++nt) {
    int col = nt*8 + qc*2;
    R[(m0+qr  )*76 + col  ] = f2tf32(acc3[nt][0]);
    R[(m0+qr  )*76 + col+1] = f2tf32(acc3[nt][1]);
    R[(m0+qr+8)*76 + col  ] = f2tf32(acc3[nt][2]);
    R[(m0+qr+8)*76 + col+1] = f2tf32(acc3[nt][3]);
  }
  __syncthreads();

  // ---- GEMM4 ----
  float acc4[16][4];
  #pragma unroll
  for (int nt=0;nt<16;++nt) {
    #pragma unroll
    for (int r=0;r<4;++r) acc4[nt][r]=0.f;
  }
  #pragma unroll
  for (int ks = 0; ks < 9; ++ks) {
    int k8 = ks*8;
    uint32_t a[4];
    a[0] = R[(m0+qr  )*76 + k8+qc  ];
    a[1] = R[(m0+qr+8)*76 + k8+qc  ];
    a[2] = R[(m0+qr  )*76 + k8+qc+4];
    a[3] = R[(m0+qr+8)*76 + k8+qc+4];
    #pragma unroll
    for (int nt=0;nt<16;++nt) {
      uint32_t bfr[2];
      bfr[0] = B4[(k8+qc  )*136 + nt*8+qr];
      bfr[1] = B4[(k8+qc+4)*136 + nt*8+qr];
      mma1688(acc4[nt], a, bfr);
    }
  }

  // epilogue: S = x + S'
  const float* xp = x + (size_t)bc*16384;
  float* Sp = g_S + (size_t)bc*16384;
  #pragma unroll
  for (int nt=0;nt<16;++nt) {
    int col = nt*8 + qc*2;
    int r0 = m0 + qr, r1 = m0 + qr + 8;
    float2 x0 = *(const float2*)&xp[r0*128 + col];
    float2 x1 = *(const float2*)&xp[r1*128 + col];
    float2 s0, s1;
    s0.x = x0.x + acc4[nt][0]; s0.y = x0.y + acc4[nt][1];
    s1.x = x1.x + acc4[nt][2]; s1.y = x1.y + acc4[nt][3];
    *(float2*)&Sp[r0*128 + col] = s0;
    *(float2*)&Sp[r1*128 + col] = s1;
  }
}

// ---------------------------------------------------------------------------
// K6 (mma.sync TF32): out[b,o,hw] = x[b,o,hw] + sum_c fw[o,c] * S[b,c,hw]
// ---------------------------------------------------------------------------
#define AS_STRIDE 20
#define BS_STRIDE 136

__global__ __launch_bounds__(256) void k6_fuse_mma(const float* __restrict__ x,
                                                   const float* __restrict__ fw,
                                                   float* __restrict__ out) {
  __shared__ uint32_t As[128*AS_STRIDE];
  __shared__ uint32_t Bs[16*BS_STRIDE];
  int tid = threadIdx.x;
  int lane = tid & 31, wid = tid >> 5;
  int bx = blockIdx.x;
  int hwT = (bx & 127) * 128;
  int t2 = bx >> 7;
  int oT = (t2 & 3) * 128;
  int b  = t2 >> 2;
  const float* Sb = g_S + (size_t)b*CC*16384;

  int wm = (wid & 3) * 32;
  int wn = (wid >> 2) * 64;
  int qr = lane >> 2;
  int qc = lane & 3;

  float acc[2][8][4];
  #pragma unroll
  for (int mt=0;mt<2;++mt) {
    #pragma unroll
    for (int nt=0;nt<8;++nt) {
      #pragma unroll
      for (int r=0;r<4;++r) acc[mt][nt][r]=0.f;
    }
  }

  for (int ch = 0; ch < 32; ++ch) {
    int c0 = ch * 16;
    #pragma unroll
    for (int it = 0; it < 2; ++it) {
      int slot = it*256 + tid;
      int o = slot >> 2, k4 = slot & 3;
      float4 v = *(const float4*)&fw[(size_t)(oT+o)*512 + c0 + k4*4];
      uint32_t* dst = &As[o*AS_STRIDE + k4*4];
      dst[0]=f2tf32(v.x); dst[1]=f2tf32(v.y); dst[2]=f2tf32(v.z); dst[3]=f2tf32(v.w);
    }
    #pragma unroll
    for (int it = 0; it < 2; ++it) {
      int slot = it*256 + tid;
      int k = slot >> 5, h4 = slot & 31;
      float4 v = *(const float4*)&Sb[(size_t)(c0+k)*16384 + hwT + h4*4];
      uint32_t* dst = &Bs[k*BS_STRIDE + h4*4];
      dst[0]=f2tf32(v.x); dst[1]=f2tf32(v.y); dst[2]=f2tf32(v.z); dst[3]=f2tf32(v.w);
    }
    __syncthreads();

    #pragma unroll
    for (int ks = 0; ks < 16; ks += 8) {
      uint32_t afr[2][4];
      #pragma unroll
      for (int mt=0;mt<2;++mt) {
        int rb = wm + mt*16;
        afr[mt][0] = As[(rb + qr     )*AS_STRIDE + ks + qc    ];
        afr[mt][1] = As[(rb + qr + 8 )*AS_STRIDE + ks + qc    ];
        afr[mt][2] = As[(rb + qr     )*AS_STRIDE + ks + qc + 4];
        afr[mt][3] = As[(rb + qr + 8 )*AS_STRIDE + ks + qc + 4];
      }
      #pragma unroll
      for (int nt=0;nt<8;++nt) {
        int cb = wn + nt*8;
        uint32_t bfr[2];
        bfr[0] = Bs[(ks + qc    )*BS_STRIDE + cb + qr];
        bfr[1] = Bs[(ks + qc + 4)*BS_STRIDE + cb + qr];
        mma1688(acc[0][nt], afr[0], bfr);
        mma1688(acc[1][nt], afr[1], bfr);
      }
    }
    __syncthreads();
  }

  #pragma unroll
  for (int mt=0;mt<2;++mt) {
    int row0 = oT + wm + mt*16 + qr;
    #pragma unroll
    for (int nt=0;nt<8;++nt) {
      int col = hwT + wn + nt*8 + qc*2;
      size_t ob0 = ((size_t)(b*512 + row0    ))*16384 + col;
      size_t ob1 = ((size_t)(b*512 + row0 + 8))*16384 + col;
      float2 x0 = *(const float2*)&x[ob0];
      float2 x1 = *(const float2*)&x[ob1];
      float2 r0, r1;
      r0.x = x0.x + acc[mt][nt][0]; r0.y = x0.y + acc[mt][nt][1];
      r1.x = x1.x + acc[mt][nt][2]; r1.y = x1.y + acc[mt][nt][3];
      *(float2*)&out[ob0] = r0;
      *(float2*)&out[ob1] = r1;
    }
  }
}

// ---------------------------------------------------------------------------
extern "C" void kernel_launch(void* const* d_in, const int* in_sizes, int n_in,
                              void* d_out, int out_size) {
  const float* x   = (const float*)d_in[0];
  const float* w1r = (const float*)d_in[1];
  const float* w1i = (const float*)d_in[2];
  const float* b1r = (const float*)d_in[3];
  const float* b1i = (const float*)d_in[4];
  const float* w2r = (const float*)d_in[5];
  const float* w2i = (const float*)d_in[6];
  const float* b2r = (const float*)d_in[7];
  const float* b2i = (const float*)d_in[8];
  const float* fw  = (const float*)d_in[9];
  float* out = (float*)d_out;

  cudaFuncSetAttribute(k12_fwd, cudaFuncAttributeMaxDynamicSharedMemorySize, 92160);
  cudaFuncSetAttribute(k45_inv, cudaFuncAttributeMaxDynamicSharedMemorySize, 96512);
  cudaFuncSetAttribute(k3_mlp,  cudaFuncAttributeMaxDynamicSharedMemorySize, 100352);

  k0_twiddle<<<32, 256>>>();
  k12_fwd<<<BB*CC, 256, 92160>>>(x);
  k3_mlp<<<NBK*132, 256, 100352>>>(w1r, w1i, b1r, b1i, w2r, w2i, b2r, b2i);
  k45_inv<<<BB*CC, 256, 96512>>>(x);
  k6_fuse_mma<<<BB*4*128, 256>>>(x, fw, out);
}

// round 10
// speedup vs baseline: 2.5599x; 1.2333x over previous
#include <cuda_runtime.h>
#include <math.h>
#include <stdint.h>

#define BB   4
#define CC   512
#define NBK  8
#define BSZ  64
#define WFM  33
#define KHM  64
#define NPTS (BB*KHM*WFM)     // 8448

// ------------------------- static device scratch ---------------------------
// Z/D layout: [n][i][p]  (p = b*2112 + k*33 + wf) -> contiguous per image
__device__ float  g_Zr[NBK*BSZ*NPTS];
__device__ float  g_Zi[NBK*BSZ*NPTS];
__device__ float  g_Dr[NBK*BSZ*NPTS];
__device__ float  g_Di[NBK*BSZ*NPTS];
__device__ float  g_S[BB*CC*128*128];

// twiddle tables (tf32 bit patterns)
__device__ uint32_t T1g[128*72];
__device__ uint32_t T2g[128*128];
__device__ uint32_t T3g[128*128];
__device__ uint32_t T4g[72*136];

__device__ __forceinline__ uint32_t f2tf32(float f) {
  uint32_t r; asm("cvt.rna.tf32.f32 %0, %1;" : "=r"(r) : "f"(f)); return r;
}
__device__ __forceinline__ void mma1688(float* d, const uint32_t* a, const uint32_t* b2) {
  asm volatile(
    "mma.sync.aligned.m16n8k8.row.col.f32.tf32.tf32.f32 "
    "{%0,%1,%2,%3}, {%4,%5,%6,%7}, {%8,%9}, {%0,%1,%2,%3};"
    : "+f"(d[0]), "+f"(d[1]), "+f"(d[2]), "+f"(d[3])
    : "r"(a[0]), "r"(a[1]), "r"(a[2]), "r"(a[3]), "r"(b2[0]), "r"(b2[1]));
}

// ---------------------------------------------------------------------------
// K0: build twiddle tables (tf32).
// ---------------------------------------------------------------------------
__global__ __launch_bounds__(256) void k0_twiddle() {
  int tid = blockIdx.x*256 + threadIdx.x;
  for (int idx = tid; idx < 128*72; idx += 256*32) {
    int w = idx / 72, nf = idx % 72;
    float v = 0.f;
    if (nf < 33)      v =  cospif((float)((w*nf) & 127) * (1.0f/64.0f));
    else if (nf < 66) v = -sinpif((float)((w*(nf-33)) & 127) * (1.0f/64.0f));
    T1g[idx] = f2tf32(v);
  }
  for (int idx = tid; idx < 128*128; idx += 256*32) {
    int m = idx >> 7, h = idx & 127;
    float v = (m < 64) ? cospif((float)((h*m) & 127) * (1.0f/64.0f))
                       : sinpif((float)((h*(m-64)) & 127) * (1.0f/64.0f));
    T2g[idx] = f2tf32(v);
  }
  for (int idx = tid; idx < 128*128; idx += 256*32) {
    int h = idx >> 7, kk = idx & 127;
    float v = (kk < 64) ? cospif((float)((h*kk) & 127) * (1.0f/64.0f))
                        : sinpif((float)((h*(kk-64)) & 127) * (1.0f/64.0f));
    T3g[idx] = f2tf32(v);
  }
  for (int idx = tid; idx < 72*136; idx += 256*32) {
    int kk = idx / 136, w = idx % 136;
    float v = 0.f;
    if (w < 128) {
      if (kk == 0)       v = 1.0f/128.0f;
      else if (kk < 33)  v =  (1.0f/64.0f) * cospif((float)((w*kk) & 127) * (1.0f/64.0f));
      else if (kk == 33) v = 0.f;
      else if (kk < 66)  v = -(1.0f/64.0f) * sinpif((float)((w*(kk-33)) & 127) * (1.0f/64.0f));
    }
    T4g[idx] = f2tf32(v);
  }
}

// ---------------------------------------------------------------------------
// K12: fused forward (GEMM1 + GEMM2 + Z scatter, now contiguous)
// ---------------------------------------------------------------------------
__global__ __launch_bounds__(256) void k12_fwd(const float* __restrict__ x) {
  extern __shared__ uint32_t smw[];
  uint32_t* As = smw;            // [128][36]
  uint32_t* B1 = smw + 4608;     // [128][72] T1 / O2f staging
  uint32_t* B2 = smw + 13824;    // [128][72]
  float* O2f = (float*)B1;

  int tid = threadIdx.x;
  int lane = tid & 31, wid = tid >> 5;
  int qr = lane >> 2, qc = lane & 3;
  int m0 = wid * 16;
  int bc = blockIdx.x;
  int b = bc >> 9, c = bc & 511;
  const float* xp = x + (size_t)bc * 16384;

  for (int i = tid; i < 9216; i += 256) B1[i] = T1g[i];

  float acc[9][4];
  #pragma unroll
  for (int nt=0;nt<9;++nt) {
    #pragma unroll
    for (int r=0;r<4;++r) acc[nt][r]=0.f;
  }
  for (int kc = 0; kc < 128; kc += 32) {
    __syncthreads();
    #pragma unroll
    for (int it = 0; it < 16; ++it) {
      int s = it*256 + tid;
      int h = s >> 5, w = s & 31;
      As[h*36 + w] = f2tf32(xp[h*128 + kc + w]);
    }
    __syncthreads();
    #pragma unroll
    for (int ks = 0; ks < 4; ++ks) {
      int k8 = ks*8;
      uint32_t a[4];
      a[0] = As[(m0+qr  )*36 + k8+qc  ];
      a[1] = As[(m0+qr+8)*36 + k8+qc  ];
      a[2] = As[(m0+qr  )*36 + k8+qc+4];
      a[3] = As[(m0+qr+8)*36 + k8+qc+4];
      #pragma unroll
      for (int nt=0;nt<9;++nt) {
        uint32_t bfr[2];
        bfr[0] = B1[(kc+k8+qc  )*72 + nt*8+qr];
        bfr[1] = B1[(kc+k8+qc+4)*72 + nt*8+qr];
        mma1688(acc[nt], a, bfr);
      }
    }
  }
  __syncthreads();
  #pragma unroll
  for (int nt=0;nt<9;++nt) {
    int col = nt*8 + qc*2;
    B2[(m0+qr  )*72 + col  ] = f2tf32(acc[nt][0]);
    B2[(m0+qr  )*72 + col+1] = f2tf32(acc[nt][1]);
    B2[(m0+qr+8)*72 + col  ] = f2tf32(acc[nt][2]);
    B2[(m0+qr+8)*72 + col+1] = f2tf32(acc[nt][3]);
  }

  #pragma unroll
  for (int nt=0;nt<9;++nt) {
    #pragma unroll
    for (int r=0;r<4;++r) acc[nt][r]=0.f;
  }
  for (int kc = 0; kc < 128; kc += 32) {
    __syncthreads();
    #pragma unroll
    for (int it = 0; it < 16; ++it) {
      int s = it*256 + tid;
      int m = s >> 5, h = s & 31;
      As[m*36 + h] = T2g[m*128 + kc + h];
    }
    __syncthreads();
    #pragma unroll
    for (int ks = 0; ks < 4; ++ks) {
      int k8 = ks*8;
      uint32_t a[4];
      a[0] = As[(m0+qr  )*36 + k8+qc  ];
      a[1] = As[(m0+qr+8)*36 + k8+qc  ];
      a[2] = As[(m0+qr  )*36 + k8+qc+4];
      a[3] = As[(m0+qr+8)*36 + k8+qc+4];
      #pragma unroll
      for (int nt=0;nt<9;++nt) {
        uint32_t bfr[2];
        bfr[0] = B2[(kc+k8+qc  )*72 + nt*8+qr];
        bfr[1] = B2[(kc+k8+qc+4)*72 + nt*8+qr];
        mma1688(acc[nt], a, bfr);
      }
    }
  }
  __syncthreads();
  #pragma unroll
  for (int nt=0;nt<9;++nt) {
    int col = nt*8 + qc*2;
    O2f[(m0+qr  )*72 + col  ] = acc[nt][0];
    O2f[(m0+qr  )*72 + col+1] = acc[nt][1];
    O2f[(m0+qr+8)*72 + col  ] = acc[nt][2];
    O2f[(m0+qr+8)*72 + col+1] = acc[nt][3];
  }
  __syncthreads();

  int n = c >> 6, i2 = c & 63;
  size_t zo = ((size_t)n*BSZ + i2)*NPTS + (size_t)b*2112;
  for (int idx = tid; idx < 2112; idx += 256) {
    int k = idx / 33, wf = idx % 33;
    float zr = (O2f[k*72 + wf] + O2f[(64+k)*72 + 33+wf]) * 0.0078125f;
    float zi = (O2f[k*72 + 33+wf] - O2f[(64+k)*72 + wf]) * 0.0078125f;
    g_Zr[zo + idx] = zr;
    g_Zi[zo + idx] = zi;
  }
}

// ---------------------------------------------------------------------------
// K3: D = softshrink(W2 @ gelu(W1 @ z + b1) + b2) - z   (layout [n][i][p])
// ---------------------------------------------------------------------------
__device__ __forceinline__ float gelu_f(float v) {
  return 0.5f*v*(1.0f + erff(v*0.70710678118654752f));
}
__device__ __forceinline__ float sshrink_f(float v) {
  float a = fabsf(v) - 0.01f;
  return a > 0.0f ? copysignf(a, v) : 0.0f;
}

__global__ __launch_bounds__(256) void k3_mlp(
    const float* __restrict__ w1r, const float* __restrict__ w1i,
    const float* __restrict__ b1r, const float* __restrict__ b1i,
    const float* __restrict__ w2r, const float* __restrict__ w2i,
    const float* __restrict__ b2r, const float* __restrict__ b2i) {
  extern __shared__ float sm3[];
  float* wsr = sm3;            float* wsi = sm3 + 4096;
  float* zsr = sm3 + 8192;     float* zsi = sm3 + 12352;   // [64 p][65]
  float* hsr = sm3 + 16512;    float* hsi = sm3 + 20672;
  float* bs  = sm3 + 24832;
  int bx = blockIdx.x;
  int n = bx / 132, pt = bx % 132;
  int tid = threadIdx.x;
  size_t nbase = (size_t)n*BSZ*NPTS + (size_t)pt*64;

  for (int idx = tid; idx < 4096; idx += 256) {
    int i = idx >> 6, pl = idx & 63;       // coalesced: pl fast
    float vr = g_Zr[nbase + (size_t)i*NPTS + pl];
    float vi = g_Zi[nbase + (size_t)i*NPTS + pl];
    zsr[pl*65 + i] = vr;
    zsi[pl*65 + i] = vi;
    wsr[idx] = w1r[n*4096 + idx]; wsi[idx] = w1i[n*4096 + idx];
  }
  if (tid < 64) {
    bs[tid]     = b1r[n*64+tid]; bs[64+tid]  = b1i[n*64+tid];
    bs[128+tid] = b2r[n*64+tid]; bs[192+tid] = b2i[n*64+tid];
  }
  __syncthreads();

  int j0 = (tid & 15) * 4, p0 = (tid >> 4) * 4;
  float hr[4][4], hi2[4][4];
  #pragma unroll
  for (int u=0;u<4;++u) {
    #pragma unroll
    for (int v=0;v<4;++v){ hr[u][v]=bs[j0+v]; hi2[u][v]=bs[64+j0+v]; }
  }

  for (int i = 0; i < 64; ++i) {
    float zr[4], zi2[4], wr[4], wi2[4];
    #pragma unroll
    for (int u=0;u<4;++u){ zr[u]=zsr[(p0+u)*65+i]; zi2[u]=zsi[(p0+u)*65+i]; }
    float4 w4r = *(float4*)&wsr[i*64+j0];
    float4 w4i = *(float4*)&wsi[i*64+j0];
    wr[0]=w4r.x; wr[1]=w4r.y; wr[2]=w4r.z; wr[3]=w4r.w;
    wi2[0]=w4i.x; wi2[1]=w4i.y; wi2[2]=w4i.z; wi2[3]=w4i.w;
    #pragma unroll
    for (int u=0;u<4;++u) {
      #pragma unroll
      for (int v=0;v<4;++v){
        hr[u][v]  += zr[u]*wr[v]  - zi2[u]*wi2[v];
        hi2[u][v] += zr[u]*wi2[v] + zi2[u]*wr[v];
      }
    }
  }
  #pragma unroll
  for (int u=0;u<4;++u) {
    #pragma unroll
    for (int v=0;v<4;++v){
      hsr[(p0+u)*65 + j0+v] = gelu_f(hr[u][v]);
      hsi[(p0+u)*65 + j0+v] = gelu_f(hi2[u][v]);
    }
  }
  __syncthreads();
  for (int idx = tid; idx < 4096; idx += 256) {
    wsr[idx] = w2r[n*4096 + idx]; wsi[idx] = w2i[n*4096 + idx];
  }
  __syncthreads();

  float yr[4][4], yi[4][4];
  #pragma unroll
  for (int u=0;u<4;++u) {
    #pragma unroll
    for (int v=0;v<4;++v){ yr[u][v]=bs[128+j0+v]; yi[u][v]=bs[192+j0+v]; }
  }

  for (int i = 0; i < 64; ++i) {
    float ar[4], ai[4], wr[4], wi2[4];
    #pragma unroll
    for (int u=0;u<4;++u){ ar[u]=hsr[(p0+u)*65+i]; ai[u]=hsi[(p0+u)*65+i]; }
    float4 w4r = *(float4*)&wsr[i*64+j0];
    float4 w4i = *(float4*)&wsi[i*64+j0];
    wr[0]=w4r.x; wr[1]=w4r.y; wr[2]=w4r.z; wr[3]=w4r.w;
    wi2[0]=w4i.x; wi2[1]=w4i.y; wi2[2]=w4i.z; wi2[3]=w4i.w;
    #pragma unroll
    for (int u=0;u<4;++u) {
      #pragma unroll
      for (int v=0;v<4;++v){
        yr[u][v] += ar[u]*wr[v]  - ai[u]*wi2[v];
        yi[u][v] += ar[u]*wi2[v] + ai[u]*wr[v];
      }
    }
  }
  // store transposed: float4 along p for each i (coalesced-ish, contiguous 16B)
  #pragma unroll
  for (int v=0;v<4;++v) {
    float4 dr, di;
    dr.x = sshrink_f(yr[0][v]) - zsr[(p0+0)*65 + j0+v];
    dr.y = sshrink_f(yr[1][v]) - zsr[(p0+1)*65 + j0+v];
    dr.z = sshrink_f(yr[2][v]) - zsr[(p0+2)*65 + j0+v];
    dr.w = sshrink_f(yr[3][v]) - zsr[(p0+3)*65 + j0+v];
    di.x = sshrink_f(yi[0][v]) - zsi[(p0+0)*65 + j0+v];
    di.y = sshrink_f(yi[1][v]) - zsi[(p0+1)*65 + j0+v];
    di.z = sshrink_f(yi[2][v]) - zsi[(p0+2)*65 + j0+v];
    di.w = sshrink_f(yi[3][v]) - zsi[(p0+3)*65 + j0+v];
    size_t ob = nbase + (size_t)(j0+v)*NPTS + p0;
    *(float4*)(g_Dr+ob) = dr;
    *(float4*)(g_Di+ob) = di;
  }
}

// ---------------------------------------------------------------------------
// K45: fused inverse (contiguous D gather)
// ---------------------------------------------------------------------------
__global__ __launch_bounds__(256) void k45_inv(const float* __restrict__ x) {
  extern __shared__ uint32_t smw[];
  uint32_t* As  = smw;            // [128][36]
  uint32_t* R   = smw + 4608;     // B3 [128][72] then As4 [128][76]
  uint32_t* B4  = smw + 14336;    // [72][136]

  int tid = threadIdx.x;
  int lane = tid & 31, wid = tid >> 5;
  int qr = lane >> 2, qc = lane & 3;
  int m0 = wid * 16;
  int bc = blockIdx.x;
  int b = bc >> 9, c = bc & 511;
  int n = c >> 6, i = c & 63;

  for (int idx = tid; idx < 9792; idx += 256) B4[idx] = T4g[idx];

  size_t dofs = ((size_t)n*BSZ + i)*NPTS + (size_t)b*2112;
  for (int idx = tid; idx < 2112; idx += 256) {
    int k = idx / 33, wf = idx % 33;
    float dr = g_Dr[dofs + idx], di = g_Di[dofs + idx];
    R[(k   )*72 + wf   ] = f2tf32(dr);
    R[(64+k)*72 + wf   ] = f2tf32(-di);
    R[(k   )*72 + 33+wf] = f2tf32(di);
    R[(64+k)*72 + 33+wf] = f2tf32(dr);
  }
  for (int idx = tid; idx < 128*6; idx += 256) {
    R[(idx/6)*72 + 66 + (idx % 6)] = 0u;
  }

  float acc3[9][4];
  #pragma unroll
  for (int nt=0;nt<9;++nt) {
    #pragma unroll
    for (int r=0;r<4;++r) acc3[nt][r]=0.f;
  }
  for (int kc = 0; kc < 128; kc += 32) {
    __syncthreads();
    #pragma unroll
    for (int it = 0; it < 16; ++it) {
      int s = it*256 + tid;
      int h = s >> 5, kl = s & 31;
      As[h*36 + kl] = T3g[h*128 + kc + kl];
    }
    __syncthreads();
    #pragma unroll
    for (int ks = 0; ks < 4; ++ks) {
      int k8 = ks*8;
      uint32_t a[4];
      a[0] = As[(m0+qr  )*36 + k8+qc  ];
      a[1] = As[(m0+qr+8)*36 + k8+qc  ];
      a[2] = As[(m0+qr  )*36 + k8+qc+4];
      a[3] = As[(m0+qr+8)*36 + k8+qc+4];
      #pragma unroll
      for (int nt=0;nt<9;++nt) {
        uint32_t bfr[2];
        bfr[0] = R[(kc+k8+qc  )*72 + nt*8+qr];
        bfr[1] = R[(kc+k8+qc+4)*72 + nt*8+qr];
        mma1688(acc3[nt], a, bfr);
      }
    }
  }
  __syncthreads();
  #pragma unroll
  for (int nt=0;nt<9;++nt) {
    int col = nt*8 + qc*2;
    R[(m0+qr  )*76 + col  ] = f2tf32(acc3[nt][0]);
    R[(m0+qr  )*76 + col+1] = f2tf32(acc3[nt][1]);
    R[(m0+qr+8)*76 + col  ] = f2tf32(acc3[nt][2]);
    R[(m0+qr+8)*76 + col+1] = f2tf32(acc3[nt][3]);
  }
  __syncthreads();

  float acc4[16][4];
  #pragma unroll
  for (int nt=0;nt<16;++nt) {
    #pragma unroll
    for (int r=0;r<4;++r) acc4[nt][r]=0.f;
  }
  #pragma unroll
  for (int ks = 0; ks < 9; ++ks) {
    int k8 = ks*8;
    uint32_t a[4];
    a[0] = R[(m0+qr  )*76 + k8+qc  ];
    a[1] = R[(m0+qr+8)*76 + k8+qc  ];
    a[2] = R[(m0+qr  )*76 + k8+qc+4];
    a[3] = R[(m0+qr+8)*76 + k8+qc+4];
    #pragma unroll
    for (int nt=0;nt<16;++nt) {
      uint32_t bfr[2];
      bfr[0] = B4[(k8+qc  )*136 + nt*8+qr];
      bfr[1] = B4[(k8+qc+4)*136 + nt*8+qr];
      mma1688(acc4[nt], a, bfr);
    }
  }

  const float* xp = x + (size_t)bc*16384;
  float* Sp = g_S + (size_t)bc*16384;
  #pragma unroll
  for (int nt=0;nt<16;++nt) {
    int col = nt*8 + qc*2;
    int r0 = m0 + qr, r1 = m0 + qr + 8;
    float2 x0 = *(const float2*)&xp[r0*128 + col];
    float2 x1 = *(const float2*)&xp[r1*128 + col];
    float2 s0, s1;
    s0.x = x0.x + acc4[nt][0]; s0.y = x0.y + acc4[nt][1];
    s1.x = x1.x + acc4[nt][2]; s1.y = x1.y + acc4[nt][3];
    *(float2*)&Sp[r0*128 + col] = s0;
    *(float2*)&Sp[r1*128 + col] = s1;
  }
}

// ---------------------------------------------------------------------------
// K6 (mma.sync TF32 + cp.async double buffer, K-chunk 32)
// smem: A0[128*36] A1[128*36] B0[32*136] B1[32*136] floats (raw fp32 staged,
// tf32 cvt at fragment load time). 71680 B dynamic.
// ---------------------------------------------------------------------------
#define K6_A0 0
#define K6_A1 4608
#define K6_B0 9216
#define K6_B1 13568
#define K6_SMEM 71680

__device__ __forceinline__ void cpa16(uint32_t dst, const void* src) {
  asm volatile("cp.async.ca.shared.global [%0], [%1], 16;" :: "r"(dst), "l"(src));
}

__global__ __launch_bounds__(256) void k6_fuse_mma(const float* __restrict__ x,
                                                   const float* __restrict__ fw,
                                                   float* __restrict__ out) {
  extern __shared__ float sm6[];
  uint32_t smb;
  asm("{ .reg .u64 t; cvta.to.shared.u64 t, %1; cvt.u32.u64 %0, t; }"
      : "=r"(smb) : "l"(sm6));
  int tid = threadIdx.x;
  int lane = tid & 31, wid = tid >> 5;
  int bx = blockIdx.x;
  int hwT = (bx & 127) * 128;
  int t2 = bx >> 7;
  int oT = (t2 & 3) * 128;
  int b  = t2 >> 2;
  const float* Sb = g_S + (size_t)b*CC*16384;

  int wm = (wid & 3) * 32;
  int wn = (wid >> 2) * 64;
  int qr = lane >> 2;
  int qc = lane & 3;

  float acc[2][8][4];
  #pragma unroll
  for (int mt=0;mt<2;++mt) {
    #pragma unroll
    for (int nt=0;nt<8;++nt) {
      #pragma unroll
      for (int r=0;r<4;++r) acc[mt][nt][r]=0.f;
    }
  }

  // chunk loader: A 1024 float4 (4/thread), B 1024 float4 (4/thread)
  auto load_chunk = [&](int ch) {
    int c0 = ch * 32;
    int aoff = (ch & 1) ? K6_A1 : K6_A0;
    int boff = (ch & 1) ? K6_B1 : K6_B0;
    #pragma unroll
    for (int it = 0; it < 4; ++it) {
      int slot = it*256 + tid;
      int o = slot >> 3, k4 = slot & 7;
      cpa16(smb + (uint32_t)(aoff + o*36 + k4*4)*4u,
            &fw[(size_t)(oT+o)*512 + c0 + k4*4]);
    }
    #pragma unroll
    for (int it = 0; it < 4; ++it) {
      int slot = it*256 + tid;
      int k = slot >> 5, h4 = slot & 31;
      cpa16(smb + (uint32_t)(boff + k*136 + h4*4)*4u,
            &Sb[(size_t)(c0+k)*16384 + hwT + h4*4]);
    }
    asm volatile("cp.async.commit_group;" ::: "memory");
  };

  load_chunk(0);
  for (int ch = 0; ch < 16; ++ch) {
    if (ch < 15) {
      load_chunk(ch + 1);
      asm volatile("cp.async.wait_group 1;" ::: "memory");
    } else {
      asm volatile("cp.async.wait_group 0;" ::: "memory");
    }
    __syncthreads();
    const float* Af = sm6 + ((ch & 1) ? K6_A1 : K6_A0);
    const float* Bf = sm6 + ((ch & 1) ? K6_B1 : K6_B0);
    #pragma unroll
    for (int ks = 0; ks < 32; ks += 8) {
      uint32_t afr[2][4];
      #pragma unroll
      for (int mt=0;mt<2;++mt) {
        int rb = wm + mt*16;
        afr[mt][0] = f2tf32(Af[(rb + qr     )*36 + ks + qc    ]);
        afr[mt][1] = f2tf32(Af[(rb + qr + 8 )*36 + ks + qc    ]);
        afr[mt][2] = f2tf32(Af[(rb + qr     )*36 + ks + qc + 4]);
        afr[mt][3] = f2tf32(Af[(rb + qr + 8 )*36 + ks + qc + 4]);
      }
      #pragma unroll
      for (int nt=0;nt<8;++nt) {
        int cb = wn + nt*8;
        uint32_t bfr[2];
        bfr[0] = f2tf32(Bf[(ks + qc    )*136 + cb + qr]);
        bfr[1] = f2tf32(Bf[(ks + qc + 4)*136 + cb + qr]);
        mma1688(acc[0][nt], afr[0], bfr);
        mma1688(acc[1][nt], afr[1], bfr);
      }
    }
    __syncthreads();
  }

  #pragma unroll
  for (int mt=0;mt<2;++mt) {
    int row0 = oT + wm + mt*16 + qr;
    #pragma unroll
    for (int nt=0;nt<8;++nt) {
      int col = hwT + wn + nt*8 + qc*2;
      size_t ob0 = ((size_t)(b*512 + row0    ))*16384 + col;
      size_t ob1 = ((size_t)(b*512 + row0 + 8))*16384 + col;
      float2 x0 = *(const float2*)&x[ob0];
      float2 x1 = *(const float2*)&x[ob1];
      float2 r0, r1;
      r0.x = x0.x + acc[mt][nt][0]; r0.y = x0.y + acc[mt][nt][1];
      r1.x = x1.x + acc[mt][nt][2]; r1.y = x1.y + acc[mt][nt][3];
      *(float2*)&out[ob0] = r0;
      *(float2*)&out[ob1] = r1;
    }
  }
}

// ---------------------------------------------------------------------------
extern "C" void kernel_launch(void* const* d_in, const int* in_sizes, int n_in,
                              void* d_out, int out_size) {
  const float* x   = (const float*)d_in[0];
  const float* w1r = (const float*)d_in[1];
  const float* w1i = (const float*)d_in[2];
  const float* b1r = (const float*)d_in[3];
  const float* b1i = (const float*)d_in[4];
  const float* w2r = (const float*)d_in[5];
  const float* w2i = (const float*)d_in[6];
  const float* b2r = (const float*)d_in[7];
  const float* b2i = (const float*)d_in[8];
  const float* fw  = (const float*)d_in[9];
  float* out = (float*)d_out;

  cudaFuncSetAttribute(k12_fwd, cudaFuncAttributeMaxDynamicSharedMemorySize, 92160);
  cudaFuncSetAttribute(k45_inv, cudaFuncAttributeMaxDynamicSharedMemorySize, 96512);
  cudaFuncSetAttribute(k3_mlp,  cudaFuncAttributeMaxDynamicSharedMemorySize, 100352);
  cudaFuncSetAttribute(k6_fuse_mma, cudaFuncAttributeMaxDynamicSharedMemorySize, K6_SMEM);

  k0_twiddle<<<32, 256>>>();
  k12_fwd<<<BB*CC, 256, 92160>>>(x);
  k3_mlp<<<NBK*132, 256, 100352>>>(w1r, w1i, b1r, b1i, w2r, w2i, b2r, b2i);
  k45_inv<<<BB*CC, 256, 96512>>>(x);
  k6_fuse_mma<<<BB*4*128, 256, K6_SMEM>>>(x, fw, out);
}

// round 11
// speedup vs baseline: 2.7196x; 1.0624x over previous
#include <cuda_runtime.h>
#include <math.h>
#include <stdint.h>

#define BB   4
#define CC   512
#define NBK  8
#define BSZ  64
#define WFM  33
#define KHM  64
#define NPTS (BB*KHM*WFM)     // 8448

// Z/D layout: [n][i][p]  (p = b*2112 + k*33 + wf) -> contiguous per image
__device__ float  g_Zr[NBK*BSZ*NPTS];
__device__ float  g_Zi[NBK*BSZ*NPTS];
__device__ float  g_Dr[NBK*BSZ*NPTS];
__device__ float  g_Di[NBK*BSZ*NPTS];
__device__ float  g_S[BB*CC*128*128];

__device__ uint32_t T1g[128*72];
__device__ uint32_t T2g[128*128];
__device__ uint32_t T3g[128*128];
__device__ uint32_t T4g[72*136];

__device__ __forceinline__ uint32_t f2tf32(float f) {
  uint32_t r; asm("cvt.rna.tf32.f32 %0, %1;" : "=r"(r) : "f"(f)); return r;
}
__device__ __forceinline__ void mma1688(float* d, const uint32_t* a, const uint32_t* b2) {
  asm volatile(
    "mma.sync.aligned.m16n8k8.row.col.f32.tf32.tf32.f32 "
    "{%0,%1,%2,%3}, {%4,%5,%6,%7}, {%8,%9}, {%0,%1,%2,%3};"
    : "+f"(d[0]), "+f"(d[1]), "+f"(d[2]), "+f"(d[3])
    : "r"(a[0]), "r"(a[1]), "r"(a[2]), "r"(a[3]), "r"(b2[0]), "r"(b2[1]));
}

// ---------------------------------------------------------------------------
__global__ __launch_bounds__(256) void k0_twiddle() {
  int tid = blockIdx.x*256 + threadIdx.x;
  for (int idx = tid; idx < 128*72; idx += 256*32) {
    int w = idx / 72, nf = idx % 72;
    float v = 0.f;
    if (nf < 33)      v =  cospif((float)((w*nf) & 127) * (1.0f/64.0f));
    else if (nf < 66) v = -sinpif((float)((w*(nf-33)) & 127) * (1.0f/64.0f));
    T1g[idx] = f2tf32(v);
  }
  for (int idx = tid; idx < 128*128; idx += 256*32) {
    int m = idx >> 7, h = idx & 127;
    float v = (m < 64) ? cospif((float)((h*m) & 127) * (1.0f/64.0f))
                       : sinpif((float)((h*(m-64)) & 127) * (1.0f/64.0f));
    T2g[idx] = f2tf32(v);
  }
  for (int idx = tid; idx < 128*128; idx += 256*32) {
    int h = idx >> 7, kk = idx & 127;
    float v = (kk < 64) ? cospif((float)((h*kk) & 127) * (1.0f/64.0f))
                        : sinpif((float)((h*(kk-64)) & 127) * (1.0f/64.0f));
    T3g[idx] = f2tf32(v);
  }
  for (int idx = tid; idx < 72*136; idx += 256*32) {
    int kk = idx / 136, w = idx % 136;
    float v = 0.f;
    if (w < 128) {
      if (kk == 0)       v = 1.0f/128.0f;
      else if (kk < 33)  v =  (1.0f/64.0f) * cospif((float)((w*kk) & 127) * (1.0f/64.0f));
      else if (kk == 33) v = 0.f;
      else if (kk < 66)  v = -(1.0f/64.0f) * sinpif((float)((w*(kk-33)) & 127) * (1.0f/64.0f));
    }
    T4g[idx] = f2tf32(v);
  }
}

// ---------------------------------------------------------------------------
// K12: fused forward (GEMM1 + GEMM2 + contiguous Z scatter)
// ---------------------------------------------------------------------------
__global__ __launch_bounds__(256) void k12_fwd(const float* __restrict__ x) {
  extern __shared__ uint32_t smw[];
  uint32_t* As = smw;            // [128][36]
  uint32_t* B1 = smw + 4608;     // [128][72]
  uint32_t* B2 = smw + 13824;    // [128][72]
  float* O2f = (float*)B1;

  int tid = threadIdx.x;
  int lane = tid & 31, wid = tid >> 5;
  int qr = lane >> 2, qc = lane & 3;
  int m0 = wid * 16;
  int bc = blockIdx.x;
  int b = bc >> 9, c = bc & 511;
  const float* xp = x + (size_t)bc * 16384;

  for (int i = tid; i < 9216; i += 256) B1[i] = T1g[i];

  float acc[9][4];
  #pragma unroll
  for (int nt=0;nt<9;++nt) {
    #pragma unroll
    for (int r=0;r<4;++r) acc[nt][r]=0.f;
  }
  for (int kc = 0; kc < 128; kc += 32) {
    __syncthreads();
    #pragma unroll
    for (int it = 0; it < 16; ++it) {
      int s = it*256 + tid;
      int h = s >> 5, w = s & 31;
      As[h*36 + w] = f2tf32(xp[h*128 + kc + w]);
    }
    __syncthreads();
    #pragma unroll
    for (int ks = 0; ks < 4; ++ks) {
      int k8 = ks*8;
      uint32_t a[4];
      a[0] = As[(m0+qr  )*36 + k8+qc  ];
      a[1] = As[(m0+qr+8)*36 + k8+qc  ];
      a[2] = As[(m0+qr  )*36 + k8+qc+4];
      a[3] = As[(m0+qr+8)*36 + k8+qc+4];
      #pragma unroll
      for (int nt=0;nt<9;++nt) {
        uint32_t bfr[2];
        bfr[0] = B1[(kc+k8+qc  )*72 + nt*8+qr];
        bfr[1] = B1[(kc+k8+qc+4)*72 + nt*8+qr];
        mma1688(acc[nt], a, bfr);
      }
    }
  }
  __syncthreads();
  #pragma unroll
  for (int nt=0;nt<9;++nt) {
    int col = nt*8 + qc*2;
    B2[(m0+qr  )*72 + col  ] = f2tf32(acc[nt][0]);
    B2[(m0+qr  )*72 + col+1] = f2tf32(acc[nt][1]);
    B2[(m0+qr+8)*72 + col  ] = f2tf32(acc[nt][2]);
    B2[(m0+qr+8)*72 + col+1] = f2tf32(acc[nt][3]);
  }

  #pragma unroll
  for (int nt=0;nt<9;++nt) {
    #pragma unroll
    for (int r=0;r<4;++r) acc[nt][r]=0.f;
  }
  for (int kc = 0; kc < 128; kc += 32) {
    __syncthreads();
    #pragma unroll
    for (int it = 0; it < 16; ++it) {
      int s = it*256 + tid;
      int m = s >> 5, h = s & 31;
      As[m*36 + h] = T2g[m*128 + kc + h];
    }
    __syncthreads();
    #pragma unroll
    for (int ks = 0; ks < 4; ++ks) {
      int k8 = ks*8;
      uint32_t a[4];
      a[0] = As[(m0+qr  )*36 + k8+qc  ];
      a[1] = As[(m0+qr+8)*36 + k8+qc  ];
      a[2] = As[(m0+qr  )*36 + k8+qc+4];
      a[3] = As[(m0+qr+8)*36 + k8+qc+4];
      #pragma unroll
      for (int nt=0;nt<9;++nt) {
        uint32_t bfr[2];
        bfr[0] = B2[(kc+k8+qc  )*72 + nt*8+qr];
        bfr[1] = B2[(kc+k8+qc+4)*72 + nt*8+qr];
        mma1688(acc[nt], a, bfr);
      }
    }
  }
  __syncthreads();
  #pragma unroll
  for (int nt=0;nt<9;++nt) {
    int col = nt*8 + qc*2;
    O2f[(m0+qr  )*72 + col  ] = acc[nt][0];
    O2f[(m0+qr  )*72 + col+1] = acc[nt][1];
    O2f[(m0+qr+8)*72 + col  ] = acc[nt][2];
    O2f[(m0+qr+8)*72 + col+1] = acc[nt][3];
  }
  __syncthreads();

  int n = c >> 6, i2 = c & 63;
  size_t zo = ((size_t)n*BSZ + i2)*NPTS + (size_t)b*2112;
  for (int idx = tid; idx < 2112; idx += 256) {
    int k = idx / 33, wf = idx % 33;
    float zr = (O2f[k*72 + wf] + O2f[(64+k)*72 + 33+wf]) * 0.0078125f;
    float zi = (O2f[k*72 + 33+wf] - O2f[(64+k)*72 + wf]) * 0.0078125f;
    g_Zr[zo + idx] = zr;
    g_Zi[zo + idx] = zi;
  }
}

// ---------------------------------------------------------------------------
// K3 (tf32 mma): complex MLP via real-stacked GEMMs.
// A = [zr|zi] (64p x 128k, k-major stride-72), B = [[wr,wi],[-wi,wr]] (128x128)
// ---------------------------------------------------------------------------
__device__ __forceinline__ float gelu_f(float v) {
  return 0.5f*v*(1.0f + erff(v*0.70710678118654752f));
}
__device__ __forceinline__ float sshrink_f(float v) {
  float a = fabsf(v) - 0.01f;
  return a > 0.0f ? copysignf(a, v) : 0.0f;
}

__global__ __launch_bounds__(256) void k3_mma(
    const float* __restrict__ w1r, const float* __restrict__ w1i,
    const float* __restrict__ b1r, const float* __restrict__ b1i,
    const float* __restrict__ w2r, const float* __restrict__ w2i,
    const float* __restrict__ b2r, const float* __restrict__ b2i) {
  extern __shared__ float sm3f[];
  uint32_t* Asu = (uint32_t*)sm3f;          // [128 k][72 p]
  float*    Asf = sm3f;                      // reused fp32 at the end
  uint32_t* Bsu = (uint32_t*)sm3f + 9216;   // [32 k][136 n]
  float*    bs  = sm3f + 13568;              // 256 biases
  int tid = threadIdx.x;
  int lane = tid & 31, wid = tid >> 5;
  int qr = lane >> 2, qc = lane & 3;
  int wm = (wid & 3) * 16;      // 4 warps along M (64)
  int wn = (wid >> 2) * 64;     // 2 warps along N (128)
  int bx = blockIdx.x;
  int nb = bx / 132, pt = bx % 132;
  size_t nbase = (size_t)nb*BSZ*NPTS + (size_t)pt*64;

  // gather z -> As (k-major, tf32)
  for (int idx = tid; idx < 4096; idx += 256) {
    int i = idx >> 6, p = idx & 63;
    Asu[i*72 + p]      = f2tf32(g_Zr[nbase + (size_t)i*NPTS + p]);
    Asu[(64+i)*72 + p] = f2tf32(g_Zi[nbase + (size_t)i*NPTS + p]);
  }
  if (tid < 64) {
    bs[tid]     = b1r[nb*64+tid]; bs[64+tid]  = b1i[nb*64+tid];
    bs[128+tid] = b2r[nb*64+tid]; bs[192+tid] = b2i[nb*64+tid];
  }

  float acc[8][4];

  #pragma unroll
  for (int layer = 0; layer < 2; ++layer) {
    const float* wr_ = layer ? w2r : w1r;
    const float* wi_ = layer ? w2i : w1i;
    #pragma unroll
    for (int nt=0;nt<8;++nt) {
      #pragma unroll
      for (int r=0;r<4;++r) acc[nt][r]=0.f;
    }
    for (int c0 = 0; c0 < 128; c0 += 32) {
      __syncthreads();
      // load stacked W chunk rows c0..c0+31 -> Bs[32][136]
      #pragma unroll
      for (int it = 0; it < 4; ++it) {
        int slot = it*256 + tid;          // 1024 float4 slots
        int kl = slot >> 5, c4 = slot & 31;
        int k = c0 + kl;
        float4 v; float sg = 1.f;
        if (k < 64) {
          if (c4 < 16) v = *(const float4*)&wr_[(size_t)nb*4096 + k*64 + c4*4];
          else         v = *(const float4*)&wi_[(size_t)nb*4096 + k*64 + (c4-16)*4];
        } else {
          int i = k - 64;
          if (c4 < 16) { v = *(const float4*)&wi_[(size_t)nb*4096 + i*64 + c4*4]; sg = -1.f; }
          else         v = *(const float4*)&wr_[(size_t)nb*4096 + i*64 + (c4-16)*4];
        }
        uint32_t* dst = &Bsu[kl*136 + c4*4];
        dst[0]=f2tf32(sg*v.x); dst[1]=f2tf32(sg*v.y);
        dst[2]=f2tf32(sg*v.z); dst[3]=f2tf32(sg*v.w);
      }
      __syncthreads();
      #pragma unroll
      for (int ks = 0; ks < 32; ks += 8) {
        uint32_t a[4];
        a[0] = Asu[(c0+ks+qc  )*72 + wm+qr  ];
        a[1] = Asu[(c0+ks+qc  )*72 + wm+qr+8];
        a[2] = Asu[(c0+ks+qc+4)*72 + wm+qr  ];
        a[3] = Asu[(c0+ks+qc+4)*72 + wm+qr+8];
        #pragma unroll
        for (int nt=0;nt<8;++nt) {
          uint32_t bfr[2];
          bfr[0] = Bsu[(ks+qc  )*136 + wn+nt*8+qr];
          bfr[1] = Bsu[(ks+qc+4)*136 + wn+nt*8+qr];
          mma1688(acc[nt], a, bfr);
        }
      }
    }
    __syncthreads();
    if (layer == 0) {
      // gelu(h + b1) -> As (tf32, k-major: row = output col j)
      #pragma unroll
      for (int nt=0;nt<8;++nt) {
        int j = wn + nt*8 + qc*2;
        Asu[(j  )*72 + wm+qr  ] = f2tf32(gelu_f(acc[nt][0] + bs[j  ]));
        Asu[(j+1)*72 + wm+qr  ] = f2tf32(gelu_f(acc[nt][1] + bs[j+1]));
        Asu[(j  )*72 + wm+qr+8] = f2tf32(gelu_f(acc[nt][2] + bs[j  ]));
        Asu[(j+1)*72 + wm+qr+8] = f2tf32(gelu_f(acc[nt][3] + bs[j+1]));
      }
    } else {
      // sshrink(y + b2) -> As (fp32)
      #pragma unroll
      for (int nt=0;nt<8;++nt) {
        int j = wn + nt*8 + qc*2;
        Asf[(j  )*72 + wm+qr  ] = sshrink_f(acc[nt][0] + bs[128+j  ]);
        Asf[(j+1)*72 + wm+qr  ] = sshrink_f(acc[nt][1] + bs[128+j+1]);
        Asf[(j  )*72 + wm+qr+8] = sshrink_f(acc[nt][2] + bs[128+j  ]);
        Asf[(j+1)*72 + wm+qr+8] = sshrink_f(acc[nt][3] + bs[128+j+1]);
      }
    }
  }
  __syncthreads();
  // D = y' - z (z re-read fp32), contiguous stores
  for (int idx = tid; idx < 8192; idx += 256) {
    int j = idx >> 6, p = idx & 63;
    float y = Asf[j*72 + p];
    if (j < 64) {
      size_t o = nbase + (size_t)j*NPTS + p;
      g_Dr[o] = y - g_Zr[o];
    } else {
      size_t o = nbase + (size_t)(j-64)*NPTS + p;
      g_Di[o] = y - g_Zi[o];
    }
  }
}

// ---------------------------------------------------------------------------
// K45: fused inverse (contiguous D gather)
// ---------------------------------------------------------------------------
__global__ __launch_bounds__(256) void k45_inv(const float* __restrict__ x) {
  extern __shared__ uint32_t smw[];
  uint32_t* As  = smw;            // [128][36]
  uint32_t* R   = smw + 4608;     // B3 [128][72] then As4 [128][76]
  uint32_t* B4  = smw + 14336;    // [72][136]

  int tid = threadIdx.x;
  int lane = tid & 31, wid = tid >> 5;
  int qr = lane >> 2, qc = lane & 3;
  int m0 = wid * 16;
  int bc = blockIdx.x;
  int b = bc >> 9, c = bc & 511;
  int n = c >> 6, i = c & 63;

  for (int idx = tid; idx < 9792; idx += 256) B4[idx] = T4g[idx];

  size_t dofs = ((size_t)n*BSZ + i)*NPTS + (size_t)b*2112;
  for (int idx = tid; idx < 2112; idx += 256) {
    int k = idx / 33, wf = idx % 33;
    float dr = g_Dr[dofs + idx], di = g_Di[dofs + idx];
    R[(k   )*72 + wf   ] = f2tf32(dr);
    R[(64+k)*72 + wf   ] = f2tf32(-di);
    R[(k   )*72 + 33+wf] = f2tf32(di);
    R[(64+k)*72 + 33+wf] = f2tf32(dr);
  }
  for (int idx = tid; idx < 128*6; idx += 256) {
    R[(idx/6)*72 + 66 + (idx % 6)] = 0u;
  }

  float acc3[9][4];
  #pragma unroll
  for (int nt=0;nt<9;++nt) {
    #pragma unroll
    for (int r=0;r<4;++r) acc3[nt][r]=0.f;
  }
  for (int kc = 0; kc < 128; kc += 32) {
    __syncthreads();
    #pragma unroll
    for (int it = 0; it < 16; ++it) {
      int s = it*256 + tid;
      int h = s >> 5, kl = s & 31;
      As[h*36 + kl] = T3g[h*128 + kc + kl];
    }
    __syncthreads();
    #pragma unroll
    for (int ks = 0; ks < 4; ++ks) {
      int k8 = ks*8;
      uint32_t a[4];
      a[0] = As[(m0+qr  )*36 + k8+qc  ];
      a[1] = As[(m0+qr+8)*36 + k8+qc  ];
      a[2] = As[(m0+qr  )*36 + k8+qc+4];
      a[3] = As[(m0+qr+8)*36 + k8+qc+4];
      #pragma unroll
      for (int nt=0;nt<9;++nt) {
        uint32_t bfr[2];
        bfr[0] = R[(kc+k8+qc  )*72 + nt*8+qr];
        bfr[1] = R[(kc+k8+qc+4)*72 + nt*8+qr];
        mma1688(acc3[nt], a, bfr);
      }
    }
  }
  __syncthreads();
  #pragma unroll
  for (int nt=0;nt<9;++nt) {
    int col = nt*8 + qc*2;
    R[(m0+qr  )*76 + col  ] = f2tf32(acc3[nt][0]);
    R[(m0+qr  )*76 + col+1] = f2tf32(acc3[nt][1]);
    R[(m0+qr+8)*76 + col  ] = f2tf32(acc3[nt][2]);
    R[(m0+qr+8)*76 + col+1] = f2tf32(acc3[nt][3]);
  }
  __syncthreads();

  float acc4[16][4];
  #pragma unroll
  for (int nt=0;nt<16;++nt) {
    #pragma unroll
    for (int r=0;r<4;++r) acc4[nt][r]=0.f;
  }
  #pragma unroll
  for (int ks = 0; ks < 9; ++ks) {
    int k8 = ks*8;
    uint32_t a[4];
    a[0] = R[(m0+qr  )*76 + k8+qc  ];
    a[1] = R[(m0+qr+8)*76 + k8+qc  ];
    a[2] = R[(m0+qr  )*76 + k8+qc+4];
    a[3] = R[(m0+qr+8)*76 + k8+qc+4];
    #pragma unroll
    for (int nt=0;nt<16;++nt) {
      uint32_t bfr[2];
      bfr[0] = B4[(k8+qc  )*136 + nt*8+qr];
      bfr[1] = B4[(k8+qc+4)*136 + nt*8+qr];
      mma1688(acc4[nt], a, bfr);
    }
  }

  const float* xp = x + (size_t)bc*16384;
  float* Sp = g_S + (size_t)bc*16384;
  #pragma unroll
  for (int nt=0;nt<16;++nt) {
    int col = nt*8 + qc*2;
    int r0 = m0 + qr, r1 = m0 + qr + 8;
    float2 x0 = *(const float2*)&xp[r0*128 + col];
    float2 x1 = *(const float2*)&xp[r1*128 + col];
    float2 s0, s1;
    s0.x = x0.x + acc4[nt][0]; s0.y = x0.y + acc4[nt][1];
    s1.x = x1.x + acc4[nt][2]; s1.y = x1.y + acc4[nt][3];
    *(float2*)&Sp[r0*128 + col] = s0;
    *(float2*)&Sp[r1*128 + col] = s1;
  }
}

// ---------------------------------------------------------------------------
// K6: 256-o-row tiles, 512 threads (8 warps M x 2 warps N), cp.async 2-stage
// ---------------------------------------------------------------------------
#define K6_A0 0
#define K6_A1 9216
#define K6_B0 18432
#define K6_B1 22784
#define K6_SMEM 108544

__device__ __forceinline__ void cpa16(uint32_t dst, const void* src) {
  asm volatile("cp.async.ca.shared.global [%0], [%1], 16;" :: "r"(dst), "l"(src));
}

__global__ __launch_bounds__(512) void k6_fuse_mma(const float* __restrict__ x,
                                                   const float* __restrict__ fw,
                                                   float* __restrict__ out) {
  extern __shared__ float sm6[];
  uint32_t smb;
  asm("{ .reg .u64 t; cvta.to.shared.u64 t, %1; cvt.u32.u64 %0, t; }"
      : "=r"(smb) : "l"(sm6));
  int tid = threadIdx.x;
  int lane = tid & 31, wid = tid >> 5;
  int bx = blockIdx.x;
  int hwT = (bx & 127) * 128;
  int t2 = bx >> 7;
  int oT = (t2 & 1) * 256;
  int b  = t2 >> 1;
  const float* Sb = g_S + (size_t)b*CC*16384;

  int wm = (wid & 7) * 32;     // 8 warps M over 256 rows
  int wn = (wid >> 3) * 64;    // 2 warps N over 128 cols
  int qr = lane >> 2;
  int qc = lane & 3;

  float acc[2][8][4];
  #pragma unroll
  for (int mt=0;mt<2;++mt) {
    #pragma unroll
    for (int nt=0;nt<8;++nt) {
      #pragma unroll
      for (int r=0;r<4;++r) acc[mt][nt][r]=0.f;
    }
  }

  auto load_chunk = [&](int ch) {
    int c0 = ch * 32;
    int aoff = (ch & 1) ? K6_A1 : K6_A0;
    int boff = (ch & 1) ? K6_B1 : K6_B0;
    #pragma unroll
    for (int it = 0; it < 4; ++it) {
      int slot = it*512 + tid;           // 2048 float4: 256 o x 8 k4
      int o = slot >> 3, k4 = slot & 7;
      cpa16(smb + (uint32_t)(aoff + o*36 + k4*4)*4u,
            &fw[(size_t)(oT+o)*512 + c0 + k4*4]);
    }
    #pragma unroll
    for (int it = 0; it < 2; ++it) {
      int slot = it*512 + tid;           // 1024 float4: 32 k x 32 h4
      int k = slot >> 5, h4 = slot & 31;
      cpa16(smb + (uint32_t)(boff + k*136 + h4*4)*4u,
            &Sb[(size_t)(c0+k)*16384 + hwT + h4*4]);
    }
    asm volatile("cp.async.commit_group;" ::: "memory");
  };

  load_chunk(0);
  for (int ch = 0; ch < 16; ++ch) {
    if (ch < 15) {
      load_chunk(ch + 1);
      asm volatile("cp.async.wait_group 1;" ::: "memory");
    } else {
      asm volatile("cp.async.wait_group 0;" ::: "memory");
    }
    __syncthreads();
    const float* Af = sm6 + ((ch & 1) ? K6_A1 : K6_A0);
    const float* Bf = sm6 + ((ch & 1) ? K6_B1 : K6_B0);
    #pragma unroll
    for (int ks = 0; ks < 32; ks += 8) {
      uint32_t afr[2][4];
      #pragma unroll
      for (int mt=0;mt<2;++mt) {
        int rb = wm + mt*16;
        afr[mt][0] = f2tf32(Af[(rb + qr     )*36 + ks + qc    ]);
        afr[mt][1] = f2tf32(Af[(rb + qr + 8 )*36 + ks + qc    ]);
        afr[mt][2] = f2tf32(Af[(rb + qr     )*36 + ks + qc + 4]);
        afr[mt][3] = f2tf32(Af[(rb + qr + 8 )*36 + ks + qc + 4]);
      }
      #pragma unroll
      for (int nt=0;nt<8;++nt) {
        int cb = wn + nt*8;
        uint32_t bfr[2];
        bfr[0] = f2tf32(Bf[(ks + qc    )*136 + cb + qr]);
        bfr[1] = f2tf32(Bf[(ks + qc + 4)*136 + cb + qr]);
        mma1688(acc[0][nt], afr[0], bfr);
        mma1688(acc[1][nt], afr[1], bfr);
      }
    }
    __syncthreads();
  }

  #pragma unroll
  for (int mt=0;mt<2;++mt) {
    int row0 = oT + wm + mt*16 + qr;
    #pragma unroll
    for (int nt=0;nt<8;++nt) {
      int col = hwT + wn + nt*8 + qc*2;
      size_t ob0 = ((size_t)(b*512 + row0    ))*16384 + col;
      size_t ob1 = ((size_t)(b*512 + row0 + 8))*16384 + col;
      float2 x0 = *(const float2*)&x[ob0];
      float2 x1 = *(const float2*)&x[ob1];
      float2 r0, r1;
      r0.x = x0.x + acc[mt][nt][0]; r0.y = x0.y + acc[mt][nt][1];
      r1.x = x1.x + acc[mt][nt][2]; r1.y = x1.y + acc[mt][nt][3];
      *(float2*)&out[ob0] = r0;
      *(float2*)&out[ob1] = r1;
    }
  }
}

// ---------------------------------------------------------------------------
extern "C" void kernel_launch(void* const* d_in, const int* in_sizes, int n_in,
                              void* d_out, int out_size) {
  const float* x   = (const float*)d_in[0];
  const float* w1r = (const float*)d_in[1];
  const float* w1i = (const float*)d_in[2];
  const float* b1r = (const float*)d_in[3];
  const float* b1i = (const float*)d_in[4];
  const float* w2r = (const float*)d_in[5];
  const float* w2i = (const float*)d_in[6];
  const float* b2r = (const float*)d_in[7];
  const float* b2i = (const float*)d_in[8];
  const float* fw  = (const float*)d_in[9];
  float* out = (float*)d_out;

  cudaFuncSetAttribute(k12_fwd, cudaFuncAttributeMaxDynamicSharedMemorySize, 92160);
  cudaFuncSetAttribute(k45_inv, cudaFuncAttributeMaxDynamicSharedMemorySize, 96512);
  cudaFuncSetAttribute(k3_mma,  cudaFuncAttributeMaxDynamicSharedMemorySize, 55296);
  cudaFuncSetAttribute(k6_fuse_mma, cudaFuncAttributeMaxDynamicSharedMemorySize, K6_SMEM);

  k0_twiddle<<<32, 256>>>();
  k12_fwd<<<BB*CC, 256, 92160>>>(x);
  k3_mma<<<NBK*132, 256, 55296>>>(w1r, w1i, b1r, b1i, w2r, w2i, b2r, b2i);
  k45_inv<<<BB*CC, 256, 96512>>>(x);
  k6_fuse_mma<<<BB*2*128, 512, K6_SMEM>>>(x, fw, out);
}